// round 5
// baseline (speedup 1.0000x reference)
#include <cuda_runtime.h>
#include <cstdint>
#include <cstdio>

// Dual LSTM: B=512, T=128, I=128, H=512.
// One persistent kernel, 128 CTAs (all co-resident on 148 SMs), custom grid
// barrier once per timestep. TF32 mma.sync GEMM, c-state in registers,
// h ping-pong through device-global buffers with .cg (L2-coherent) access.

#define B_   512
#define T_   128
#define I_   128
#define H_   512
#define K_   640     // I + H
#define G4_  2048    // 4*H

#define MT   128     // batch rows per CTA
#define NT   32      // hidden cols per CTA (x4 gates = 128 gate cols)
#define NBLK 128
#define NTHREADS 256

#define SMEM_BYTES 66560

// persistent state
__device__ float    g_h[2][2][B_ * H_];   // [cell][parity][B*H]
__device__ unsigned g_arrive = 0;
__device__ unsigned g_release = 0;

__device__ __forceinline__ unsigned f2tf32(float x) {
    unsigned u;
    asm("cvt.rna.tf32.f32 %0, %1;" : "=r"(u) : "f"(x));
    return u;
}

__device__ __forceinline__ void mma8(float* d, const unsigned* a, const unsigned* b) {
    asm volatile(
        "mma.sync.aligned.m16n8k8.row.col.f32.tf32.tf32.f32 "
        "{%0,%1,%2,%3}, {%4,%5,%6,%7}, {%8,%9}, {%0,%1,%2,%3};\n"
        : "+f"(d[0]), "+f"(d[1]), "+f"(d[2]), "+f"(d[3])
        : "r"(a[0]), "r"(a[1]), "r"(a[2]), "r"(a[3]), "r"(b[0]), "r"(b[1]));
}

__device__ __forceinline__ void grid_sync() {
    __syncthreads();
    if (threadIdx.x == 0) {
        __threadfence();
        unsigned ticket = atomicAdd(&g_arrive, 1u) + 1u;
        unsigned target = (ticket + NBLK - 1u) / NBLK;   // generation to wait for
        if (ticket == target * NBLK) {
            atomicAdd(&g_release, 1u);                   // last arriver releases
        }
        unsigned r;
        for (;;) {
            asm volatile("ld.acquire.gpu.u32 %0, [%1];" : "=r"(r) : "l"(&g_release) : "memory");
            if (r >= target) break;
            __nanosleep(64);
        }
    }
    __syncthreads();
}

__device__ __forceinline__ float sigm(float x) { return 1.0f / (1.0f + expf(-x)); }

extern "C" __global__ void __launch_bounds__(NTHREADS, 1)
dual_lstm_kernel(const float* __restrict__ s_x, const float* __restrict__ l_x,
                 const float* __restrict__ s_W, const float* __restrict__ s_b,
                 const float* __restrict__ l_W, const float* __restrict__ l_b,
                 const float* __restrict__ oW,  const float* __restrict__ ob,
                 float* __restrict__ out)
{
    extern __shared__ unsigned char smem_raw[];
    unsigned* As = (unsigned*)smem_raw;     // [128][36] tf32
    unsigned* Bs = As + 128 * 36;           // [32][132] tf32
    float*    Gs = (float*)smem_raw;        // [128][128] gate exchange (reuses As/Bs)

    const int tid  = threadIdx.x;
    const int bid  = blockIdx.x;
    const int cell = bid >> 6;              // 0 = short, 1 = long
    const int rr   = bid & 63;
    const int mt   = rr >> 4;               // 0..3
    const int nt   = rr & 15;               // 0..15
    const int b0   = mt * MT;
    const int n0   = nt * NT;

    const float* x  = cell ? l_x : s_x;
    const float* W  = cell ? l_W : s_W;
    const float* bb = cell ? l_b : s_b;

    const int warp = tid >> 5, lane = tid & 31;
    const int wm = warp >> 2, wn = warp & 3;    // warp tile: 64 rows x 32 cols

    // ---- zero initial h (parity 0) for this CTA's owned patch ----
    {
        const int col = tid & 31, rg = tid >> 5;
        #pragma unroll
        for (int i = 0; i < 16; ++i) {
            int row = rg + (i << 3);
            __stcg(&g_h[cell][0][(size_t)(b0 + row) * H_ + n0 + col], 0.0f);
        }
    }

    // c-state in registers: thread owns (rows rg+8i, col), i<16
    float c_st[16];
    #pragma unroll
    for (int i = 0; i < 16; ++i) c_st[i] = 0.0f;

    float bias4[4];
    {
        const int col = tid & 31;
        #pragma unroll
        for (int g = 0; g < 4; ++g) bias4[g] = bb[g * H_ + n0 + col];
    }

    grid_sync();   // h zeros visible everywhere

    // ================== time loop ==================
    for (int t = 0; t < T_; ++t) {
        const float* hread  = g_h[cell][t & 1];
        float*       hwrite = g_h[cell][(t + 1) & 1];

        float acc[4][4][4];
        #pragma unroll
        for (int a = 0; a < 4; ++a)
            #pragma unroll
            for (int n = 0; n < 4; ++n)
                #pragma unroll
                for (int r = 0; r < 4; ++r) acc[a][n][r] = 0.0f;

        for (int kt = 0; kt < 20; ++kt) {
            const int k0 = kt * 32;
            // ---- fill A tile [128 rows][32 k] (x for kt<4, h for kt>=4) ----
            #pragma unroll
            for (int i = 0; i < 4; ++i) {
                int e  = tid + i * 256;      // float4 index, 1024 total
                int m  = e >> 3;
                int kk = (e & 7) << 2;
                float4 v;
                if (k0 < I_) {
                    v = __ldg((const float4*)(x + (size_t)(b0 + m) * (T_ * I_) +
                                              (size_t)t * I_ + k0 + kk));
                } else {
                    v = __ldcg((const float4*)(hread + (size_t)(b0 + m) * H_ +
                                               (k0 - I_) + kk));
                }
                unsigned* d = As + m * 36 + kk;
                d[0] = f2tf32(v.x); d[1] = f2tf32(v.y);
                d[2] = f2tf32(v.z); d[3] = f2tf32(v.w);
            }
            // ---- fill B tile [32 k][128 gate-cols: 4 gates x 32] ----
            #pragma unroll
            for (int i = 0; i < 4; ++i) {
                int e   = tid + i * 256;     // float4 index, 1024 total
                int kk  = e >> 5;
                int c   = (e & 31) << 2;
                int gat = c >> 5;
                int cin = c & 31;
                float4 v = __ldg((const float4*)(W + (size_t)(k0 + kk) * G4_ +
                                                 gat * H_ + n0 + cin));
                unsigned* d = Bs + kk * 132 + c;
                d[0] = f2tf32(v.x); d[1] = f2tf32(v.y);
                d[2] = f2tf32(v.z); d[3] = f2tf32(v.w);
            }
            __syncthreads();
            // ---- compute: 4 k-chunks of 8, 16 mma each ----
            #pragma unroll
            for (int kc = 0; kc < 32; kc += 8) {
                unsigned af[4][4];
                #pragma unroll
                for (int mf = 0; mf < 4; ++mf) {
                    int rb = wm * 64 + mf * 16;
                    const unsigned* p = As + (rb + (lane >> 2)) * 36 + kc + (lane & 3);
                    af[mf][0] = p[0];
                    af[mf][1] = p[8 * 36];
                    af[mf][2] = p[4];
                    af[mf][3] = p[8 * 36 + 4];
                }
                unsigned bf[4][2];
                #pragma unroll
                for (int nf = 0; nf < 4; ++nf) {
                    int cb = wn * 32 + nf * 8;
                    const unsigned* p = Bs + (kc + (lane & 3)) * 132 + cb + (lane >> 2);
                    bf[nf][0] = p[0];
                    bf[nf][1] = p[4 * 132];
                }
                #pragma unroll
                for (int mf = 0; mf < 4; ++mf)
                    #pragma unroll
                    for (int nf = 0; nf < 4; ++nf)
                        mma8(acc[mf][nf], af[mf], bf[nf]);
            }
            __syncthreads();
        }

        // ---- dump G to smem for gate-math exchange ----
        #pragma unroll
        for (int mf = 0; mf < 4; ++mf) {
            int r0 = wm * 64 + mf * 16 + (lane >> 2);
            #pragma unroll
            for (int nf = 0; nf < 4; ++nf) {
                int cb = wn * 32 + nf * 8 + ((lane & 3) << 1);
                Gs[r0 * 128 + cb]             = acc[mf][nf][0];
                Gs[r0 * 128 + cb + 1]         = acc[mf][nf][1];
                Gs[(r0 + 8) * 128 + cb]       = acc[mf][nf][2];
                Gs[(r0 + 8) * 128 + cb + 1]   = acc[mf][nf][3];
            }
        }
        __syncthreads();

        // ---- gate math (c in registers, h to global .cg) ----
        {
            const int col = tid & 31, rg = tid >> 5;
            #pragma unroll
            for (int i = 0; i < 16; ++i) {
                int row  = rg + (i << 3);
                float f  = Gs[row * 128 +  0 + col] + bias4[0];
                float ii = Gs[row * 128 + 32 + col] + bias4[1];
                float o  = Gs[row * 128 + 64 + col] + bias4[2];
                float cd = Gs[row * 128 + 96 + col] + bias4[3];
                float c  = sigm(f) * c_st[i] + sigm(ii) * tanhf(cd);
                c_st[i]  = c;
                __stcg(&hwrite[(size_t)(b0 + row) * H_ + n0 + col],
                       sigm(o) * tanhf(c));
            }
        }
        grid_sync();
    }

    // ================== epilogue: out = tanh([sh,lh] @ oW + ob) ==================
    // final h lives in parity (T_ & 1) == 0
    const float* hs = g_h[0][0];
    const float* hl = g_h[1][0];
    const int mt2 = bid >> 4;       // 0..7
    const int nt2 = bid & 15;       // 0..15
    const int b0e = mt2 * 64;
    const int n0e = nt2 * 32;
    unsigned* As2 = (unsigned*)smem_raw;    // [64][36]
    unsigned* Bs2 = As2 + 64 * 36;          // [32][36]

    const int wm2 = warp & 3;       // rows: 4 x 16
    const int wn2 = warp >> 2;      // cols: 2 x 16
    float acc2[2][4];
    #pragma unroll
    for (int n = 0; n < 2; ++n)
        #pragma unroll
        for (int r = 0; r < 4; ++r) acc2[n][r] = 0.0f;

    for (int kt = 0; kt < 32; ++kt) {
        const int k0 = kt * 32;
        __syncthreads();
        #pragma unroll
        for (int i = 0; i < 2; ++i) {
            int e  = tid + i * 256;   // 512 float4 total
            int m  = e >> 3;
            int kk = (e & 7) << 2;
            int k  = k0 + kk;
            float4 v = (k < H_)
                ? __ldcg((const float4*)(hs + (size_t)(b0e + m) * H_ + k))
                : __ldcg((const float4*)(hl + (size_t)(b0e + m) * H_ + (k - H_)));
            unsigned* d = As2 + m * 36 + kk;
            d[0] = f2tf32(v.x); d[1] = f2tf32(v.y);
            d[2] = f2tf32(v.z); d[3] = f2tf32(v.w);
        }
        {
            int e  = tid;             // 256 float4 total
            int kk = e >> 3;
            int c  = (e & 7) << 2;
            float4 v = __ldg((const float4*)(oW + (size_t)(k0 + kk) * H_ + n0e + c));
            unsigned* d = Bs2 + kk * 36 + c;
            d[0] = f2tf32(v.x); d[1] = f2tf32(v.y);
            d[2] = f2tf32(v.z); d[3] = f2tf32(v.w);
        }
        __syncthreads();
        #pragma unroll
        for (int kc = 0; kc < 32; kc += 8) {
            unsigned af[4];
            int rb = wm2 * 16;
            const unsigned* p = As2 + (rb + (lane >> 2)) * 36 + kc + (lane & 3);
            af[0] = p[0]; af[1] = p[8 * 36]; af[2] = p[4]; af[3] = p[8 * 36 + 4];
            #pragma unroll
            for (int nf = 0; nf < 2; ++nf) {
                int cb = wn2 * 16 + nf * 8;
                const unsigned* q = Bs2 + (kc + (lane & 3)) * 36 + cb + (lane >> 2);
                unsigned bf2[2] = { q[0], q[4 * 36] };
                mma8(acc2[nf], af, bf2);
            }
        }
    }

    #pragma unroll
    for (int nf = 0; nf < 2; ++nf) {
        int row = b0e + wm2 * 16 + (lane >> 2);
        int col = n0e + wn2 * 16 + nf * 8 + ((lane & 3) << 1);
        out[(size_t)row * H_ + col]           = tanhf(acc2[nf][0] + ob[col]);
        out[(size_t)row * H_ + col + 1]       = tanhf(acc2[nf][1] + ob[col + 1]);
        out[(size_t)(row + 8) * H_ + col]     = tanhf(acc2[nf][2] + ob[col]);
        out[(size_t)(row + 8) * H_ + col + 1] = tanhf(acc2[nf][3] + ob[col + 1]);
    }
}

extern "C" void kernel_launch(void* const* d_in, const int* in_sizes, int n_in,
                              void* d_out, int out_size) {
    (void)in_sizes; (void)n_in; (void)out_size;
    const float* s_x = (const float*)d_in[0];
    const float* l_x = (const float*)d_in[1];
    // d_in[2]=dow, d_in[3]=hour : unused by the reference
    const float* s_W = (const float*)d_in[4];
    const float* s_b = (const float*)d_in[5];
    const float* l_W = (const float*)d_in[6];
    const float* l_b = (const float*)d_in[7];
    const float* oW  = (const float*)d_in[8];
    const float* ob  = (const float*)d_in[9];
    float* out = (float*)d_out;

    cudaFuncSetAttribute(dual_lstm_kernel,
                         cudaFuncAttributeMaxDynamicSharedMemorySize, SMEM_BYTES);
    dual_lstm_kernel<<<NBLK, NTHREADS, SMEM_BYTES>>>(s_x, l_x, s_W, s_b,
                                                     l_W, l_b, oW, ob, out);
}

// round 9
// speedup vs baseline: 1.0823x; 1.0823x over previous
#include <cuda_runtime.h>
#include <cstdint>

// Dual LSTM B=512 T=128 I=128 H=512 — persistent kernel, 128 CTAs x 512 thr,
// mma.sync tf32, double-buffered smem with single barrier per k-tile,
// c-state in registers, h ping-pong through L2 (.cg), grid barrier per step.

#define B_   512
#define T_   128
#define I_   128
#define H_   512
#define K_   640
#define G4_  2048

#define NBLK     128
#define NTHREADS 512

// stage layout (tf32 words): As [128][36] then Bs [32][132]
#define AS_ELEMS   (128 * 36)
#define STAGE_ELEMS (AS_ELEMS + 32 * 132)       // 8832
#define SMEM_BYTES (2 * STAGE_ELEMS * 4)        // 70656
#define GS_STRIDE  133

__device__ float    g_h[2][2][B_ * H_];
__device__ unsigned g_arrive[4];
__device__ unsigned g_release[4];

__device__ __forceinline__ unsigned f2tf32(float x) {
    unsigned u; asm("cvt.rna.tf32.f32 %0, %1;" : "=r"(u) : "f"(x)); return u;
}

__device__ __forceinline__ void mma8(float* d, const unsigned* a, const unsigned* b) {
    asm volatile(
        "mma.sync.aligned.m16n8k8.row.col.f32.tf32.tf32.f32 "
        "{%0,%1,%2,%3}, {%4,%5,%6,%7}, {%8,%9}, {%0,%1,%2,%3};\n"
        : "+f"(d[0]), "+f"(d[1]), "+f"(d[2]), "+f"(d[3])
        : "r"(a[0]), "r"(a[1]), "r"(a[2]), "r"(a[3]), "r"(b[0]), "r"(b[1]));
}

__device__ __forceinline__ void gsync(int idx, unsigned n) {
    __syncthreads();
    if (threadIdx.x == 0) {
        __threadfence();
        unsigned t = atomicAdd(&g_arrive[idx], 1u) + 1u;
        unsigned gen = (t + n - 1u) / n;
        if (t == gen * n) atomicAdd(&g_release[idx], 1u);
        unsigned r;
        for (;;) {
            asm volatile("ld.acquire.gpu.u32 %0, [%1];" : "=r"(r) : "l"(&g_release[idx]) : "memory");
            if (r >= gen) break;
        }
    }
    __syncthreads();
}

__device__ __forceinline__ float sigm(float x) {
    return __fdividef(1.0f, 1.0f + __expf(-x));
}
__device__ __forceinline__ float tanh_f(float x) {
    float ax = fabsf(x);
    float e  = __expf(-2.0f * ax);
    float r  = __fdividef(1.0f - e, 1.0f + e);
    return copysignf(r, x);
}

extern "C" __global__ void __launch_bounds__(NTHREADS, 1)
dual_lstm_kernel(const float* __restrict__ s_x, const float* __restrict__ l_x,
                 const float* __restrict__ s_W, const float* __restrict__ s_b,
                 const float* __restrict__ l_W, const float* __restrict__ l_b,
                 const float* __restrict__ oW,  const float* __restrict__ ob,
                 float* __restrict__ out)
{
    extern __shared__ unsigned char smem_raw[];
    unsigned* St = (unsigned*)smem_raw;          // 2 stages
    float*    Gs = (float*)smem_raw;             // [128][133], aliases stages

    const int tid  = threadIdx.x;
    const int bid  = blockIdx.x;
    const int cell = bid >> 6;
    const int rr   = bid & 63;
    const int b0   = (rr >> 4) * 128;            // batch block
    const int n0   = (rr & 15) * 32;             // hidden block

    const float* x  = cell ? l_x : s_x;
    const float* W  = cell ? l_W : s_W;
    const float* bb = cell ? l_b : s_b;

    const int warp = tid >> 5, lane = tid & 31;
    const int wm = warp >> 2, wn = warp & 3;     // 4x4 warp grid, 32x32 warp tile

    // ---- zero initial h (parity 0) for this CTA's owned patch ----
    const int col = tid & 31, rg = tid >> 5;     // rg in [0,16)
    #pragma unroll
    for (int i = 0; i < 8; ++i) {
        int row = rg + (i << 4);
        __stcg(&g_h[cell][0][(size_t)(b0 + row) * H_ + n0 + col], 0.0f);
    }

    float c_st[8];
    #pragma unroll
    for (int i = 0; i < 8; ++i) c_st[i] = 0.0f;
    float bias4[4];
    #pragma unroll
    for (int g = 0; g < 4; ++g) bias4[g] = bb[g * H_ + n0 + col];

    gsync(cell, 64);   // h zeros visible within cell

    // ================== time loop ==================
    for (int t = 0; t < T_; ++t) {
        const float* hread  = g_h[cell][t & 1];
        float*       hwrite = g_h[cell][(t + 1) & 1];

        float acc[2][4][4];
        #pragma unroll
        for (int a = 0; a < 2; ++a)
            #pragma unroll
            for (int n = 0; n < 4; ++n)
                #pragma unroll
                for (int r = 0; r < 4; ++r) acc[a][n][r] = 0.0f;

        float4 va[2], vb[2];
        // ---- prologue: load kt=0 (k0=0 -> x), store stage 0 ----
        #pragma unroll
        for (int i = 0; i < 2; ++i) {
            int e = tid + i * 512;
            int m = e >> 3, kk = (e & 7) << 2;
            va[i] = __ldg((const float4*)(x + (size_t)(b0 + m) * (T_ * I_) +
                                          (size_t)t * I_ + kk));
            int kb = e >> 5, c = (e & 31) << 2;
            int gat = c >> 5, cin = c & 31;
            vb[i] = __ldg((const float4*)(W + (size_t)kb * G4_ + gat * H_ + n0 + cin));
        }
        {
            unsigned* As = St;
            unsigned* Bs = St + AS_ELEMS;
            #pragma unroll
            for (int i = 0; i < 2; ++i) {
                int e = tid + i * 512;
                int m = e >> 3, kk = (e & 7) << 2;
                unsigned* d = As + m * 36 + kk;
                d[0] = f2tf32(va[i].x); d[1] = f2tf32(va[i].y);
                d[2] = f2tf32(va[i].z); d[3] = f2tf32(va[i].w);
                int kb = e >> 5, c = (e & 31) << 2;
                unsigned* db = Bs + kb * 132 + c;
                db[0] = f2tf32(vb[i].x); db[1] = f2tf32(vb[i].y);
                db[2] = f2tf32(vb[i].z); db[3] = f2tf32(vb[i].w);
            }
        }
        __syncthreads();

        for (int kt = 0; kt < 20; ++kt) {
            const int s = kt & 1;
            // ---- prefetch kt+1 into registers ----
            if (kt < 19) {
                const int k0n = (kt + 1) * 32;
                #pragma unroll
                for (int i = 0; i < 2; ++i) {
                    int e = tid + i * 512;
                    int m = e >> 3, kk = (e & 7) << 2;
                    if (k0n < I_)
                        va[i] = __ldg((const float4*)(x + (size_t)(b0 + m) * (T_ * I_) +
                                                      (size_t)t * I_ + k0n + kk));
                    else
                        va[i] = __ldcg((const float4*)(hread + (size_t)(b0 + m) * H_ +
                                                       (k0n - I_) + kk));
                    int kb = e >> 5, c = (e & 31) << 2;
                    int gat = c >> 5, cin = c & 31;
                    vb[i] = __ldg((const float4*)(W + (size_t)(k0n + kb) * G4_ +
                                                  gat * H_ + n0 + cin));
                }
            }
            // ---- compute kt from stage s ----
            {
                const unsigned* As = St + s * STAGE_ELEMS;
                const unsigned* Bs = As + AS_ELEMS;
                #pragma unroll
                for (int kc = 0; kc < 32; kc += 8) {
                    unsigned af[2][4];
                    #pragma unroll
                    for (int mf = 0; mf < 2; ++mf) {
                        int rb = wm * 32 + mf * 16;
                        const unsigned* p = As + (rb + (lane >> 2)) * 36 + kc + (lane & 3);
                        af[mf][0] = p[0];
                        af[mf][1] = p[8 * 36];
                        af[mf][2] = p[4];
                        af[mf][3] = p[8 * 36 + 4];
                    }
                    unsigned bf[4][2];
                    #pragma unroll
                    for (int nf = 0; nf < 4; ++nf) {
                        int cb = wn * 32 + nf * 8;
                        const unsigned* p = Bs + (kc + (lane & 3)) * 132 + cb + (lane >> 2);
                        bf[nf][0] = p[0];
                        bf[nf][1] = p[4 * 132];
                    }
                    #pragma unroll
                    for (int mf = 0; mf < 2; ++mf)
                        #pragma unroll
                        for (int nf = 0; nf < 4; ++nf)
                            mma8(acc[mf][nf], af[mf], bf[nf]);
                }
            }
            // ---- store kt+1 into stage s^1 ----
            if (kt < 19) {
                unsigned* As = St + (s ^ 1) * STAGE_ELEMS;
                unsigned* Bs = As + AS_ELEMS;
                #pragma unroll
                for (int i = 0; i < 2; ++i) {
                    int e = tid + i * 512;
                    int m = e >> 3, kk = (e & 7) << 2;
                    unsigned* d = As + m * 36 + kk;
                    d[0] = f2tf32(va[i].x); d[1] = f2tf32(va[i].y);
                    d[2] = f2tf32(va[i].z); d[3] = f2tf32(va[i].w);
                    int kb = e >> 5, c = (e & 31) << 2;
                    unsigned* db = Bs + kb * 132 + c;
                    db[0] = f2tf32(vb[i].x); db[1] = f2tf32(vb[i].y);
                    db[2] = f2tf32(vb[i].z); db[3] = f2tf32(vb[i].w);
                }
            }
            __syncthreads();
        }

        // ---- dump G to smem for gate-math exchange ----
        #pragma unroll
        for (int mf = 0; mf < 2; ++mf) {
            int r0 = wm * 32 + mf * 16 + (lane >> 2);
            #pragma unroll
            for (int nf = 0; nf < 4; ++nf) {
                int cb = wn * 32 + nf * 8 + ((lane & 3) << 1);
                Gs[r0 * GS_STRIDE + cb]           = acc[mf][nf][0];
                Gs[r0 * GS_STRIDE + cb + 1]       = acc[mf][nf][1];
                Gs[(r0 + 8) * GS_STRIDE + cb]     = acc[mf][nf][2];
                Gs[(r0 + 8) * GS_STRIDE + cb + 1] = acc[mf][nf][3];
            }
        }
        __syncthreads();

        // ---- gate math (c in registers, h to global .cg) ----
        #pragma unroll
        for (int i = 0; i < 8; ++i) {
            int row  = rg + (i << 4);
            const float* gr = Gs + row * GS_STRIDE;
            float f  = gr[ 0 + col] + bias4[0];
            float ii = gr[32 + col] + bias4[1];
            float o  = gr[64 + col] + bias4[2];
            float cd = gr[96 + col] + bias4[3];
            float c  = sigm(f) * c_st[i] + sigm(ii) * tanh_f(cd);
            c_st[i]  = c;
            __stcg(&hwrite[(size_t)(b0 + row) * H_ + n0 + col], sigm(o) * tanh_f(c));
        }
        gsync(cell, 64);
    }

    gsync(2, 128);   // both cells' final h visible everywhere

    // ================== epilogue: out = tanh([sh,lh] @ oW + ob) ==================
    // final h lives in parity 0 (T_ even)
    const float* hs = g_h[0][0];
    const float* hl = g_h[1][0];
    const int b0e = (bid >> 4) * 64;
    const int n0e = (bid & 15) * 32;
    unsigned* As2 = (unsigned*)smem_raw;    // [64][36]
    unsigned* Bs2 = As2 + 64 * 36;          // [32][36]

    // 16 warps: 4(m) x 4(n), warp tile 16x8
    const int wm2 = warp & 3;
    const int wn2 = warp >> 2;
    const int rb2 = wm2 * 16;
    const int cb2 = wn2 * 8;
    float acc2[4];
    #pragma unroll
    for (int r = 0; r < 4; ++r) acc2[r] = 0.0f;

    for (int kt = 0; kt < 32; ++kt) {
        const int k0 = kt * 32;
        __syncthreads();
        {
            int e  = tid;                 // 512 float4 for As2
            int m  = e >> 3;
            int kk = (e & 7) << 2;
            int k  = k0 + kk;
            float4 v = (k < H_)
                ? __ldcg((const float4*)(hs + (size_t)(b0e + m) * H_ + k))
                : __ldcg((const float4*)(hl + (size_t)(b0e + m) * H_ + (k - H_)));
            unsigned* d = As2 + m * 36 + kk;
            d[0] = f2tf32(v.x); d[1] = f2tf32(v.y);
            d[2] = f2tf32(v.z); d[3] = f2tf32(v.w);
        }
        if (tid < 256) {
            int kk = tid >> 3;
            int c  = (tid & 7) << 2;
            float4 v = __ldg((const float4*)(oW + (size_t)(k0 + kk) * H_ + n0e + c));
            unsigned* d = Bs2 + kk * 36 + c;
            d[0] = f2tf32(v.x); d[1] = f2tf32(v.y);
            d[2] = f2tf32(v.z); d[3] = f2tf32(v.w);
        }
        __syncthreads();
        #pragma unroll
        for (int kc = 0; kc < 32; kc += 8) {
            unsigned af[4];
            const unsigned* p = As2 + (rb2 + (lane >> 2)) * 36 + kc + (lane & 3);
            af[0] = p[0]; af[1] = p[8 * 36]; af[2] = p[4]; af[3] = p[8 * 36 + 4];
            const unsigned* q = Bs2 + (kc + (lane & 3)) * 36 + cb2 + (lane >> 2);
            unsigned bf2[2] = { q[0], q[4 * 36] };
            mma8(acc2, af, bf2);
        }
    }

    {
        int row = b0e + rb2 + (lane >> 2);
        int c0  = n0e + cb2 + ((lane & 3) << 1);
        out[(size_t)row * H_ + c0]           = tanhf(acc2[0] + ob[c0]);
        out[(size_t)row * H_ + c0 + 1]       = tanhf(acc2[1] + ob[c0 + 1]);
        out[(size_t)(row + 8) * H_ + c0]     = tanhf(acc2[2] + ob[c0]);
        out[(size_t)(row + 8) * H_ + c0 + 1] = tanhf(acc2[3] + ob[c0 + 1]);
    }
}

extern "C" void kernel_launch(void* const* d_in, const int* in_sizes, int n_in,
                              void* d_out, int out_size) {
    (void)in_sizes; (void)n_in; (void)out_size;
    const float* s_x = (const float*)d_in[0];
    const float* l_x = (const float*)d_in[1];
    // d_in[2]=dow, d_in[3]=hour : unused by the reference
    const float* s_W = (const float*)d_in[4];
    const float* s_b = (const float*)d_in[5];
    const float* l_W = (const float*)d_in[6];
    const float* l_b = (const float*)d_in[7];
    const float* oW  = (const float*)d_in[8];
    const float* ob  = (const float*)d_in[9];
    float* out = (float*)d_out;

    cudaFuncSetAttribute(dual_lstm_kernel,
                         cudaFuncAttributeMaxDynamicSharedMemorySize, SMEM_BYTES);
    dual_lstm_kernel<<<NBLK, NTHREADS, SMEM_BYTES>>>(s_x, l_x, s_W, s_b,
                                                     l_W, l_b, oW, ob, out);
}

// round 12
// speedup vs baseline: 2.1740x; 2.0086x over previous
#include <cuda_runtime.h>
#include <cuda_fp16.h>
#include <cstdint>
#include <cstring>

// Dual LSTM B=512 T=128 I=128 H=512 — persistent kernel, 128 CTAs x 512 thr,
// fp16 mma.sync m16n8k16 (fp32 accum), prepass-converted x/W, h in fp16,
// double-buffered smem, single barrier per k-tile, grid barrier per step.

#define B_   512
#define T_   128
#define I_   128
#define H_   512
#define K_   640
#define G4_  2048

#define NBLK     128
#define NTHREADS 512

// smem stage (32-bit words): A [128 rows][20 words] + B [16 kp][136 words]
#define A_STRIDE 20
#define B_STRIDE 136
#define A_WORDS  (128 * A_STRIDE)          // 2560
#define B_WORDS  (16 * B_STRIDE)           // 2176
#define STAGE_WORDS (A_WORDS + B_WORDS)    // 4736
#define GS_STRIDE  133
#define SMEM_BYTES 69632

__device__ __half   g_x16[2][(size_t)B_ * T_ * I_];
__device__ unsigned g_W16[2][(size_t)(K_ / 2) * G4_];   // half2(W[2kp][c], W[2kp+1][c])
__device__ __half   g_h16[2][2][(size_t)B_ * H_];
__device__ unsigned g_arrive[4];
__device__ unsigned g_release[4];

__device__ __forceinline__ unsigned f2tf32(float x) {
    unsigned u; asm("cvt.rna.tf32.f32 %0, %1;" : "=r"(u) : "f"(x)); return u;
}
__device__ __forceinline__ unsigned h2_as_u32(__half2 h) {
    unsigned u;
    memcpy(&u, &h, 4);
    return u;
}

__device__ __forceinline__ void mma16(float* d, const unsigned* a, const unsigned* b) {
    asm volatile(
        "mma.sync.aligned.m16n8k16.row.col.f32.f16.f16.f32 "
        "{%0,%1,%2,%3}, {%4,%5,%6,%7}, {%8,%9}, {%0,%1,%2,%3};\n"
        : "+f"(d[0]), "+f"(d[1]), "+f"(d[2]), "+f"(d[3])
        : "r"(a[0]), "r"(a[1]), "r"(a[2]), "r"(a[3]), "r"(b[0]), "r"(b[1]));
}

__device__ __forceinline__ void mma8t(float* d, const unsigned* a, const unsigned* b) {
    asm volatile(
        "mma.sync.aligned.m16n8k8.row.col.f32.tf32.tf32.f32 "
        "{%0,%1,%2,%3}, {%4,%5,%6,%7}, {%8,%9}, {%0,%1,%2,%3};\n"
        : "+f"(d[0]), "+f"(d[1]), "+f"(d[2]), "+f"(d[3])
        : "r"(a[0]), "r"(a[1]), "r"(a[2]), "r"(a[3]), "r"(b[0]), "r"(b[1]));
}

__device__ __forceinline__ void gsync(int idx, unsigned n) {
    __syncthreads();
    if (threadIdx.x == 0) {
        __threadfence();
        unsigned t = atomicAdd(&g_arrive[idx], 1u) + 1u;
        unsigned gen = (t + n - 1u) / n;
        if (t == gen * n) atomicAdd(&g_release[idx], 1u);
        unsigned r;
        for (;;) {
            asm volatile("ld.acquire.gpu.u32 %0, [%1];" : "=r"(r) : "l"(&g_release[idx]) : "memory");
            if (r >= gen) break;
        }
    }
    __syncthreads();
}

__device__ __forceinline__ float sigm(float x) {
    return __fdividef(1.0f, 1.0f + __expf(-x));
}
__device__ __forceinline__ float tanh_f(float x) {
    float ax = fabsf(x);
    float e  = __expf(-2.0f * ax);
    float r  = __fdividef(1.0f - e, 1.0f + e);
    return copysignf(r, x);
}
__device__ __forceinline__ void st_h16(__half* p, float v) {
    unsigned short us = __half_as_ushort(__float2half_rn(v));
    asm volatile("st.global.cg.u16 [%0], %1;" :: "l"(p), "h"(us) : "memory");
}

// ---------------- prepass kernels ----------------
extern "C" __global__ void prep_x_kernel(const float* __restrict__ sx,
                                         const float* __restrict__ lx) {
    const int PER = B_ * T_ * I_ / 4;      // float4 groups per cell
    int i = blockIdx.x * blockDim.x + threadIdx.x;
    if (i >= 2 * PER) return;
    int cell = (i >= PER);
    int j = i - cell * PER;
    const float* src = cell ? lx : sx;
    float4 v = __ldg((const float4*)src + j);
    __half2* dst = (__half2*)(g_x16[cell]) + j * 2;
    dst[0] = __floats2half2_rn(v.x, v.y);
    dst[1] = __floats2half2_rn(v.z, v.w);
}

extern "C" __global__ void prep_w_kernel(const float* __restrict__ sW,
                                         const float* __restrict__ lW) {
    const int PER = (K_ / 2) * (G4_ / 4);  // threads per cell (4 cols each)
    int i = blockIdx.x * blockDim.x + threadIdx.x;
    if (i >= 2 * PER) return;
    int cell = (i >= PER);
    int r = i - cell * PER;
    int kp = r >> 9;                       // G4_/4 = 512
    int c  = (r & 511) << 2;
    const float* W = cell ? lW : sW;
    float4 v0 = __ldg((const float4*)(W + (size_t)(2 * kp) * G4_ + c));
    float4 v1 = __ldg((const float4*)(W + (size_t)(2 * kp + 1) * G4_ + c));
    uint4 o;
    o.x = h2_as_u32(__floats2half2_rn(v0.x, v1.x));
    o.y = h2_as_u32(__floats2half2_rn(v0.y, v1.y));
    o.z = h2_as_u32(__floats2half2_rn(v0.z, v1.z));
    o.w = h2_as_u32(__floats2half2_rn(v0.w, v1.w));
    *(uint4*)(&g_W16[cell][(size_t)kp * G4_ + c]) = o;
}

// ---------------- main persistent kernel ----------------
extern "C" __global__ void __launch_bounds__(NTHREADS, 1)
dual_lstm_kernel(const float* __restrict__ s_b, const float* __restrict__ l_b,
                 const float* __restrict__ oW,  const float* __restrict__ ob,
                 float* __restrict__ out)
{
    extern __shared__ unsigned char smem_raw[];
    unsigned* St = (unsigned*)smem_raw;          // 2 stages
    float*    Gs = (float*)smem_raw;             // [128][133], aliases stages

    const int tid  = threadIdx.x;
    const int bid  = blockIdx.x;
    const int cell = bid >> 6;
    const int rr   = bid & 63;
    const int b0   = (rr >> 4) * 128;            // batch block
    const int n0   = (rr & 15) * 32;             // hidden block

    const __half*   x16 = g_x16[cell];
    const unsigned* W16 = g_W16[cell];
    const float*    bb  = cell ? l_b : s_b;

    const int warp = tid >> 5, lane = tid & 31;
    const int wm = warp >> 2, wn = warp & 3;     // 4x4 warp grid, 32x32 warp tile
    const int q  = lane >> 2, cl = lane & 3;

    // ---- zero initial h (parity 0) for this CTA's owned patch ----
    const int col = tid & 31, rg = tid >> 5;
    #pragma unroll
    for (int i = 0; i < 8; ++i) {
        int row = rg + (i << 4);
        st_h16(&g_h16[cell][0][(size_t)(b0 + row) * H_ + n0 + col], 0.0f);
    }

    float c_st[8];
    #pragma unroll
    for (int i = 0; i < 8; ++i) c_st[i] = 0.0f;
    float bias4[4];
    #pragma unroll
    for (int g = 0; g < 4; ++g) bias4[g] = bb[g * H_ + n0 + col];

    gsync(cell, 64);   // h zeros (and prepass outputs) visible within cell

    // fill index precompute
    const int fa_row = tid >> 2;                 // A fill: row, 8 halves each
    const int fa_k8  = (tid & 3) << 3;           // half offset within 32-k tile
    const int fa_w   = fa_row * A_STRIDE + ((tid & 3) << 2);   // STS word addr
    const int fb_kp  = tid >> 5;                 // B fill: kp row 0..15
    const int fb_n   = (tid & 31) << 2;          // 4 half2 cols
    const int fb_gat = fb_n >> 5;
    const int fb_cin = fb_n & 31;
    const int fb_w   = fb_kp * B_STRIDE + fb_n;  // STS word addr
    const size_t fb_g = (size_t)fb_gat * H_ + n0 + fb_cin;

    // ================== time loop ==================
    for (int t = 0; t < T_; ++t) {
        const __half* hread  = g_h16[cell][t & 1];
        __half*       hwrite = g_h16[cell][(t + 1) & 1];

        float acc[2][4][4];
        #pragma unroll
        for (int a = 0; a < 2; ++a)
            #pragma unroll
            for (int n = 0; n < 4; ++n)
                #pragma unroll
                for (int r = 0; r < 4; ++r) acc[a][n][r] = 0.0f;

        uint4 va, vb;
        // ---- prologue: load kt=0 (x), store stage 0 ----
        va = __ldg((const uint4*)(x16 + ((size_t)(b0 + fa_row) * T_ + t) * I_ + fa_k8));
        vb = __ldg((const uint4*)(W16 + (size_t)fb_kp * G4_ + fb_g));
        *(uint4*)(St + fa_w) = va;
        *(uint4*)(St + A_WORDS + fb_w) = vb;
        __syncthreads();

        for (int kt = 0; kt < 20; ++kt) {
            const int s = kt & 1;
            // ---- prefetch kt+1 into registers ----
            if (kt < 19) {
                const int k0n = (kt + 1) * 32;
                if (k0n < I_)
                    va = __ldg((const uint4*)(x16 + ((size_t)(b0 + fa_row) * T_ + t) * I_ +
                                              k0n + fa_k8));
                else
                    va = __ldcg((const uint4*)(hread + (size_t)(b0 + fa_row) * H_ +
                                               (k0n - I_) + fa_k8));
                vb = __ldg((const uint4*)(W16 + (size_t)((kt + 1) * 16 + fb_kp) * G4_ + fb_g));
            }
            // ---- compute kt from stage s ----
            {
                const unsigned* As = St + s * STAGE_WORDS;
                const unsigned* Bs = As + A_WORDS;
                #pragma unroll
                for (int kc = 0; kc < 2; ++kc) {
                    const int kc8 = kc * 8;
                    unsigned af[2][4];
                    #pragma unroll
                    for (int mf = 0; mf < 2; ++mf) {
                        const unsigned* p = As + (wm * 32 + mf * 16 + q) * A_STRIDE + kc8 + cl;
                        af[mf][0] = p[0];
                        af[mf][1] = p[8 * A_STRIDE];
                        af[mf][2] = p[4];
                        af[mf][3] = p[8 * A_STRIDE + 4];
                    }
                    unsigned bf[4][2];
                    #pragma unroll
                    for (int nf = 0; nf < 4; ++nf) {
                        const unsigned* p = Bs + (kc8 + cl) * B_STRIDE + wn * 32 + nf * 8 + q;
                        bf[nf][0] = p[0];
                        bf[nf][1] = p[4 * B_STRIDE];
                    }
                    #pragma unroll
                    for (int mf = 0; mf < 2; ++mf)
                        #pragma unroll
                        for (int nf = 0; nf < 4; ++nf)
                            mma16(acc[mf][nf], af[mf], bf[nf]);
                }
            }
            // ---- store kt+1 into stage s^1 ----
            if (kt < 19) {
                unsigned* As = St + (s ^ 1) * STAGE_WORDS;
                *(uint4*)(As + fa_w) = va;
                *(uint4*)(As + A_WORDS + fb_w) = vb;
            }
            __syncthreads();
        }

        // ---- dump G to smem for gate-math exchange ----
        #pragma unroll
        for (int mf = 0; mf < 2; ++mf) {
            int r0 = wm * 32 + mf * 16 + q;
            #pragma unroll
            for (int nf = 0; nf < 4; ++nf) {
                int cb = wn * 32 + nf * 8 + (cl << 1);
                Gs[r0 * GS_STRIDE + cb]           = acc[mf][nf][0];
                Gs[r0 * GS_STRIDE + cb + 1]       = acc[mf][nf][1];
                Gs[(r0 + 8) * GS_STRIDE + cb]     = acc[mf][nf][2];
                Gs[(r0 + 8) * GS_STRIDE + cb + 1] = acc[mf][nf][3];
            }
        }
        __syncthreads();

        // ---- gate math (c in registers, h to global fp16 .cg) ----
        #pragma unroll
        for (int i = 0; i < 8; ++i) {
            int row  = rg + (i << 4);
            const float* gr = Gs + row * GS_STRIDE;
            float f  = gr[ 0 + col] + bias4[0];
            float ii = gr[32 + col] + bias4[1];
            float o  = gr[64 + col] + bias4[2];
            float cd = gr[96 + col] + bias4[3];
            float c  = sigm(f) * c_st[i] + sigm(ii) * tanh_f(cd);
            c_st[i]  = c;
            st_h16(&hwrite[(size_t)(b0 + row) * H_ + n0 + col], sigm(o) * tanh_f(c));
        }
        gsync(cell, 64);
    }

    gsync(2, 128);   // both cells' final h visible everywhere

    // ================== epilogue: out = tanh([sh,lh] @ oW + ob) ==================
    const __half* hs = g_h16[0][0];
    const __half* hl = g_h16[1][0];
    const int b0e = (bid >> 4) * 64;
    const int n0e = (bid & 15) * 32;
    unsigned* As2 = (unsigned*)smem_raw;    // [64][36] tf32
    unsigned* Bs2 = As2 + 64 * 36;          // [32][36] tf32

    const int wm2 = warp & 3;
    const int wn2 = warp >> 2;
    const int rb2 = wm2 * 16;
    const int cb2 = wn2 * 8;
    float acc2[4];
    #pragma unroll
    for (int r = 0; r < 4; ++r) acc2[r] = 0.0f;

    for (int kt = 0; kt < 32; ++kt) {
        const int k0 = kt * 32;
        __syncthreads();
        {
            int m  = tid >> 3;
            int kk = (tid & 7) << 2;
            int k  = k0 + kk;
            const __half* hp = (k < H_) ? (hs + (size_t)(b0e + m) * H_ + k)
                                        : (hl + (size_t)(b0e + m) * H_ + (k - H_));
            uint2 u = __ldcg((const uint2*)hp);
            __half2 p0, p1;
            memcpy(&p0, &u.x, 4);
            memcpy(&p1, &u.y, 4);
            unsigned* d = As2 + m * 36 + kk;
            d[0] = __float_as_uint(__low2float(p0));
            d[1] = __float_as_uint(__high2float(p0));
            d[2] = __float_as_uint(__low2float(p1));
            d[3] = __float_as_uint(__high2float(p1));
        }
        if (tid < 256) {
            int kk = tid >> 3;
            int c  = (tid & 7) << 2;
            float4 v = __ldg((const float4*)(oW + (size_t)(k0 + kk) * H_ + n0e + c));
            unsigned* d = Bs2 + kk * 36 + c;
            d[0] = f2tf32(v.x); d[1] = f2tf32(v.y);
            d[2] = f2tf32(v.z); d[3] = f2tf32(v.w);
        }
        __syncthreads();
        #pragma unroll
        for (int kc = 0; kc < 32; kc += 8) {
            unsigned af[4];
            const unsigned* p = As2 + (rb2 + q) * 36 + kc + cl;
            af[0] = p[0]; af[1] = p[8 * 36]; af[2] = p[4]; af[3] = p[8 * 36 + 4];
            const unsigned* qq = Bs2 + (kc + cl) * 36 + cb2 + q;
            unsigned bf2[2] = { qq[0], qq[4 * 36] };
            mma8t(acc2, af, bf2);
        }
    }

    {
        int row = b0e + rb2 + q;
        int c0  = n0e + cb2 + (cl << 1);
        out[(size_t)row * H_ + c0]           = tanhf(acc2[0] + ob[c0]);
        out[(size_t)row * H_ + c0 + 1]       = tanhf(acc2[1] + ob[c0 + 1]);
        out[(size_t)(row + 8) * H_ + c0]     = tanhf(acc2[2] + ob[c0]);
        out[(size_t)(row + 8) * H_ + c0 + 1] = tanhf(acc2[3] + ob[c0 + 1]);
    }
}

extern "C" void kernel_launch(void* const* d_in, const int* in_sizes, int n_in,
                              void* d_out, int out_size) {
    (void)in_sizes; (void)n_in; (void)out_size;
    const float* s_x = (const float*)d_in[0];
    const float* l_x = (const float*)d_in[1];
    // d_in[2]=dow, d_in[3]=hour : unused by the reference
    const float* s_W = (const float*)d_in[4];
    const float* s_b = (const float*)d_in[5];
    const float* l_W = (const float*)d_in[6];
    const float* l_b = (const float*)d_in[7];
    const float* oW  = (const float*)d_in[8];
    const float* ob  = (const float*)d_in[9];
    float* out = (float*)d_out;

    // prepass: convert x and W to fp16 (x: 2*B*T*I/4 float4s; W: 2*(K/2)*(G4/4))
    prep_x_kernel<<<(2 * B_ * T_ * I_ / 4 + 511) / 512, 512>>>(s_x, l_x);
    prep_w_kernel<<<(2 * (K_ / 2) * (G4_ / 4) + 511) / 512, 512>>>(s_W, l_W);

    cudaFuncSetAttribute(dual_lstm_kernel,
                         cudaFuncAttributeMaxDynamicSharedMemorySize, SMEM_BYTES);
    dual_lstm_kernel<<<NBLK, NTHREADS, SMEM_BYTES>>>(s_b, l_b, oW, ob, out);
}

// round 14
// speedup vs baseline: 2.2281x; 1.0249x over previous
#include <cuda_runtime.h>
#include <cuda_fp16.h>
#include <cstdint>
#include <cstring>

// Dual LSTM B=512 T=128 I=128 H=512 — persistent kernel, 128 CTAs x 512 thr,
// fp16 mma m16n8k16, ldmatrix fragment loads, gate-interleaved W layout so
// gate math stays in registers (no smem exchange), h as fp16 half2 via L2.

#define B_   512
#define T_   128
#define I_   128
#define H_   512
#define K_   640
#define G4_  2048

#define NBLK     128
#define NTHREADS 512

// smem stage (32-bit words): A [128 rows][20 words] + B [128 pcols][20 words]
#define A_STRIDE 20
#define B_STRIDE 20
#define A_WORDS  (128 * A_STRIDE)          // 2560
#define B_WORDS  (128 * B_STRIDE)          // 2560
#define STAGE_WORDS (A_WORDS + B_WORDS)    // 5120
#define STAGE_BYTES (STAGE_WORDS * 4)      // 20480
#define SMEM_BYTES  (2 * STAGE_BYTES)      // 40960

__device__ __half   g_x16[2][(size_t)B_ * T_ * I_];
__device__ __half   g_Wn[2][(size_t)G4_ * K_];   // [pcol][k], gate-interleaved pcol
__device__ __half   g_h16[2][2][(size_t)B_ * H_];
__device__ unsigned g_arrive[4];
__device__ unsigned g_release[4];

__device__ __forceinline__ unsigned f2tf32(float x) {
    unsigned u; asm("cvt.rna.tf32.f32 %0, %1;" : "=r"(u) : "f"(x)); return u;
}

__device__ __forceinline__ void ldsm4(unsigned* r, uint32_t a) {
    asm volatile("ldmatrix.sync.aligned.m8n8.x4.shared.b16 {%0,%1,%2,%3}, [%4];"
                 : "=r"(r[0]), "=r"(r[1]), "=r"(r[2]), "=r"(r[3]) : "r"(a));
}

__device__ __forceinline__ uint32_t smem_u32(const void* p) {
    uint32_t a;
    asm("{ .reg .u64 t; cvta.to.shared.u64 t, %1; cvt.u32.u64 %0, t; }" : "=r"(a) : "l"(p));
    return a;
}

__device__ __forceinline__ void mma16(float* d, const unsigned* a, const unsigned* b) {
    asm volatile(
        "mma.sync.aligned.m16n8k16.row.col.f32.f16.f16.f32 "
        "{%0,%1,%2,%3}, {%4,%5,%6,%7}, {%8,%9}, {%0,%1,%2,%3};\n"
        : "+f"(d[0]), "+f"(d[1]), "+f"(d[2]), "+f"(d[3])
        : "r"(a[0]), "r"(a[1]), "r"(a[2]), "r"(a[3]), "r"(b[0]), "r"(b[1]));
}

__device__ __forceinline__ void mma8t(float* d, const unsigned* a, const unsigned* b) {
    asm volatile(
        "mma.sync.aligned.m16n8k8.row.col.f32.tf32.tf32.f32 "
        "{%0,%1,%2,%3}, {%4,%5,%6,%7}, {%8,%9}, {%0,%1,%2,%3};\n"
        : "+f"(d[0]), "+f"(d[1]), "+f"(d[2]), "+f"(d[3])
        : "r"(a[0]), "r"(a[1]), "r"(a[2]), "r"(a[3]), "r"(b[0]), "r"(b[1]));
}

__device__ __forceinline__ void gsync(int idx, unsigned n) {
    __syncthreads();
    if (threadIdx.x == 0) {
        __threadfence();
        unsigned t = atomicAdd(&g_arrive[idx], 1u) + 1u;
        unsigned gen = (t + n - 1u) / n;
        if (t == gen * n) atomicAdd(&g_release[idx], 1u);
        unsigned r;
        for (;;) {
            asm volatile("ld.acquire.gpu.u32 %0, [%1];" : "=r"(r) : "l"(&g_release[idx]) : "memory");
            if (r >= gen) break;
        }
    }
    __syncthreads();
}

__device__ __forceinline__ float sigm(float x) {
    return __fdividef(1.0f, 1.0f + __expf(-x));
}
__device__ __forceinline__ float tanh_f(float x) {
    float ax = fabsf(x);
    float e  = __expf(-2.0f * ax);
    float r  = __fdividef(1.0f - e, 1.0f + e);
    return copysignf(r, x);
}
__device__ __forceinline__ void st_h2(__half* p, float v0, float v1) {
    __half2 h = __floats2half2_rn(v0, v1);
    unsigned u; memcpy(&u, &h, 4);
    asm volatile("st.global.cg.u32 [%0], %1;" :: "l"(p), "r"(u) : "memory");
}

// pcol -> (gate, global hidden col) mapping (must match main kernel fragments)
__device__ __forceinline__ void pcol_map(int pcol, int& gate, int& n) {
    int slice = pcol >> 7;
    int lp    = pcol & 127;
    int wn    = lp >> 5;
    int r     = lp & 31;
    int nf    = r >> 3;
    int p     = r & 7;
    gate = (nf & 1) * 2 + (p & 1);
    n    = slice * 32 + wn * 8 + (nf >> 1) + (p >> 1) * 2;
}

// ---------------- prepass kernels ----------------
extern "C" __global__ void prep_x_kernel(const float* __restrict__ sx,
                                         const float* __restrict__ lx) {
    const int PER = B_ * T_ * I_ / 4;
    int i = blockIdx.x * blockDim.x + threadIdx.x;
    if (i >= 2 * PER) return;
    int cell = (i >= PER);
    int j = i - cell * PER;
    const float* src = cell ? lx : sx;
    float4 v = __ldg((const float4*)src + j);
    __half2* dst = (__half2*)(g_x16[cell]) + j * 2;
    dst[0] = __floats2half2_rn(v.x, v.y);
    dst[1] = __floats2half2_rn(v.z, v.w);
}

extern "C" __global__ void prep_w_kernel(const float* __restrict__ sW,
                                         const float* __restrict__ lW) {
    // one thread per (cell, pcol, 8-k group): 2*2048*80 = 327680
    const int PER = G4_ * (K_ / 8);
    int i = blockIdx.x * blockDim.x + threadIdx.x;
    if (i >= 2 * PER) return;
    int cell = (i >= PER);
    int r = i - cell * PER;
    int pcol = r / (K_ / 8);
    int kg   = r % (K_ / 8);
    int gate, n;
    pcol_map(pcol, gate, n);
    const float* W = cell ? lW : sW;
    int wc = gate * H_ + n;
    __half tmp[8];
    #pragma unroll
    for (int k = 0; k < 8; ++k)
        tmp[k] = __float2half_rn(__ldg(W + (size_t)(kg * 8 + k) * G4_ + wc));
    uint4 o; memcpy(&o, tmp, 16);
    *(uint4*)(&g_Wn[cell][(size_t)pcol * K_ + kg * 8]) = o;
}

// ---------------- main persistent kernel ----------------
extern "C" __global__ void __launch_bounds__(NTHREADS, 1)
dual_lstm_kernel(const float* __restrict__ s_b, const float* __restrict__ l_b,
                 const float* __restrict__ oW,  const float* __restrict__ ob,
                 float* __restrict__ out)
{
    extern __shared__ unsigned char smem_raw[];
    unsigned* St = (unsigned*)smem_raw;          // 2 stages
    const uint32_t smem_b32 = smem_u32(smem_raw);

    const int tid  = threadIdx.x;
    const int bid  = blockIdx.x;
    const int cell = bid >> 6;
    const int rr   = bid & 63;
    const int b0   = (rr >> 4) * 128;            // batch block
    const int n0   = (rr & 15) * 32;             // hidden block
    const int pbase = (rr & 15) * 128;           // pcol block in g_Wn

    const __half* x16 = g_x16[cell];
    const __half* Wn  = g_Wn[cell];
    const float*  bb  = cell ? l_b : s_b;

    const int warp = tid >> 5, lane = tid & 31;
    const int wm = warp >> 2, wn = warp & 3;     // 4x4 warp grid
    const int q  = lane >> 2, cl = lane & 3;

    // thread's owned hidden cols (adjacent pair) and bias
    const int ncol0 = n0 + wn * 8 + 2 * cl;
    float bias_g[2][4];                          // [j][gate]
    #pragma unroll
    for (int j = 0; j < 2; ++j)
        #pragma unroll
        for (int g = 0; g < 4; ++g)
            bias_g[j][g] = bb[g * H_ + ncol0 + j];

    // ---- zero initial h (parity 0) for this thread's owned cells ----
    #pragma unroll
    for (int mf = 0; mf < 2; ++mf)
        #pragma unroll
        for (int r = 0; r < 2; ++r) {
            int row = b0 + wm * 32 + mf * 16 + q + r * 8;
            st_h2(&g_h16[cell][0][(size_t)row * H_ + ncol0], 0.0f, 0.0f);
        }

    float c_st[8];
    #pragma unroll
    for (int i = 0; i < 8; ++i) c_st[i] = 0.0f;

    gsync(cell, 64);   // h zeros + prepass outputs visible within cell

    // fill index precompute
    const int fa_row = tid >> 2;                 // A fill: row, 8 halves each
    const int fa_k8  = (tid & 3) << 3;
    const int fa_w   = fa_row * A_STRIDE + ((tid & 3) << 2);
    const int fb_lp  = tid >> 2;                 // B fill: pcol 0..127
    const int fb_kg  = (tid & 3) << 3;           // 8 halves of k
    const int fb_w   = A_WORDS + fb_lp * B_STRIDE + ((tid & 3) << 2);
    const __half* WnC = Wn + (size_t)(pbase + fb_lp) * K_;

    // ldmatrix address components (byte offsets within stage)
    const uint32_t a_frag_off = (uint32_t)((lane & 15) * (A_STRIDE * 4) + (lane >> 4) * 16);
    const uint32_t b_pcol     = (uint32_t)((lane >> 4) * 8 + (lane & 7));
    const uint32_t b_frag_off = (uint32_t)(A_WORDS * 4 + (wn * 32 + b_pcol) * (B_STRIDE * 4) +
                                           ((lane >> 3) & 1) * 16);
    const uint32_t sbase[2] = { smem_b32, smem_b32 + STAGE_BYTES };

    // ================== time loop ==================
    for (int t = 0; t < T_; ++t) {
        const __half* hread  = g_h16[cell][t & 1];
        __half*       hwrite = g_h16[cell][(t + 1) & 1];

        float acc[2][4][4];
        #pragma unroll
        for (int a = 0; a < 2; ++a)
            #pragma unroll
            for (int n = 0; n < 4; ++n)
                #pragma unroll
                for (int r = 0; r < 4; ++r) acc[a][n][r] = 0.0f;

        uint4 va, vb;
        // ---- prologue: load kt=0 (x), store stage 0 ----
        va = __ldg((const uint4*)(x16 + ((size_t)(b0 + fa_row) * T_ + t) * I_ + fa_k8));
        vb = __ldg((const uint4*)(WnC + fb_kg));
        *(uint4*)(St + fa_w) = va;
        *(uint4*)(St + fb_w) = vb;
        __syncthreads();

        for (int kt = 0; kt < 20; ++kt) {
            const int s = kt & 1;
            // ---- prefetch kt+1 into registers ----
            if (kt < 19) {
                const int k0n = (kt + 1) * 32;
                if (k0n < I_)
                    va = __ldg((const uint4*)(x16 + ((size_t)(b0 + fa_row) * T_ + t) * I_ +
                                              k0n + fa_k8));
                else
                    va = __ldcg((const uint4*)(hread + (size_t)(b0 + fa_row) * H_ +
                                               (k0n - I_) + fa_k8));
                vb = __ldg((const uint4*)(WnC + k0n + fb_kg));
            }
            // ---- compute kt from stage s via ldmatrix ----
            {
                const uint32_t sA = sbase[s];
                #pragma unroll
                for (int kc = 0; kc < 2; ++kc) {
                    unsigned af[2][4], bf[4][4];
                    #pragma unroll
                    for (int mf = 0; mf < 2; ++mf)
                        ldsm4(af[mf], sA + (wm * 32 + mf * 16) * (A_STRIDE * 4) +
                                       a_frag_off + kc * 32);
                    #pragma unroll
                    for (int nfp = 0; nfp < 2; ++nfp)
                        ldsm4(bf[nfp * 2], sA + b_frag_off + nfp * (16 * B_STRIDE * 4) +
                                            kc * 32);
                    // bf[2*nfp] regs: {nf_even k0-7, nf_even k8-15, nf_odd k0-7, nf_odd k8-15}
                    #pragma unroll
                    for (int mf = 0; mf < 2; ++mf) {
                        #pragma unroll
                        for (int nfp = 0; nfp < 2; ++nfp) {
                            mma16(acc[mf][nfp * 2],     af[mf], &bf[nfp * 2][0]);
                            mma16(acc[mf][nfp * 2 + 1], af[mf], &bf[nfp * 2][2]);
                        }
                    }
                }
            }
            // ---- store kt+1 into stage s^1 ----
            if (kt < 19) {
                unsigned* Ds = St + (s ^ 1) * STAGE_WORDS;
                *(uint4*)(Ds + fa_w) = va;
                *(uint4*)(Ds + fb_w) = vb;
            }
            __syncthreads();
        }

        // ---- gate math fully in registers ----
        // acc[mf][2j+gp][2r+par]: row q+8r+..., pcol parity par; gates per pcol_map
        #pragma unroll
        for (int mf = 0; mf < 2; ++mf) {
            #pragma unroll
            for (int r = 0; r < 2; ++r) {
                float h01[2];
                #pragma unroll
                for (int j = 0; j < 2; ++j) {
                    float f  = acc[mf][j * 2][2 * r]     + bias_g[j][0];
                    float ii = acc[mf][j * 2][2 * r + 1] + bias_g[j][1];
                    float o  = acc[mf][j * 2 + 1][2 * r]     + bias_g[j][2];
                    float cd = acc[mf][j * 2 + 1][2 * r + 1] + bias_g[j][3];
                    int ci = mf * 4 + r * 2 + j;
                    float c = sigm(f) * c_st[ci] + sigm(ii) * tanh_f(cd);
                    c_st[ci] = c;
                    h01[j] = sigm(o) * tanh_f(c);
                }
                int row = b0 + wm * 32 + mf * 16 + q + r * 8;
                st_h2(&hwrite[(size_t)row * H_ + ncol0], h01[0], h01[1]);
            }
        }
        gsync(cell, 64);
    }

    gsync(2, 128);   // both cells' final h visible everywhere

    // ================== epilogue: out = tanh([sh,lh] @ oW + ob) ==================
    const __half* hs = g_h16[0][0];
    const __half* hl = g_h16[1][0];
    const int b0e = (bid >> 4) * 64;
    const int n0e = (bid & 15) * 32;
    unsigned* As2 = (unsigned*)smem_raw;    // [64][36] tf32
    unsigned* Bs2 = As2 + 64 * 36;          // [32][36] tf32

    const int wm2 = warp & 3;
    const int wn2 = warp >> 2;
    const int rb2 = wm2 * 16;
    const int cb2 = wn2 * 8;
    float acc2[4];
    #pragma unroll
    for (int r = 0; r < 4; ++r) acc2[r] = 0.0f;

    for (int kt = 0; kt < 32; ++kt) {
        const int k0 = kt * 32;
        __syncthreads();
        {
            int m  = tid >> 3;
            int kk = (tid & 7) << 2;
            int k  = k0 + kk;
            const __half* hp = (k < H_) ? (hs + (size_t)(b0e + m) * H_ + k)
                                        : (hl + (size_t)(b0e + m) * H_ + (k - H_));
            uint2 u = __ldcg((const uint2*)hp);
            __half2 p0, p1;
            memcpy(&p0, &u.x, 4);
            memcpy(&p1, &u.y, 4);
            unsigned* d = As2 + m * 36 + kk;
            d[0] = __float_as_uint(__low2float(p0));
            d[1] = __float_as_uint(__high2float(p0));
            d[2] = __float_as_uint(__low2float(p1));
            d[3] = __float_as_uint(__high2float(p1));
        }
        if (tid < 256) {
            int kk = tid >> 3;
            int c  = (tid & 7) << 2;
            float4 v = __ldg((const float4*)(oW + (size_t)(k0 + kk) * H_ + n0e + c));
            unsigned* d = Bs2 + kk * 36 + c;
            d[0] = f2tf32(v.x); d[1] = f2tf32(v.y);
            d[2] = f2tf32(v.z); d[3] = f2tf32(v.w);
        }
        __syncthreads();
        #pragma unroll
        for (int kc = 0; kc < 32; kc += 8) {
            unsigned af[4];
            const unsigned* p = As2 + (rb2 + q) * 36 + kc + cl;
            af[0] = p[0]; af[1] = p[8 * 36]; af[2] = p[4]; af[3] = p[8 * 36 + 4];
            const unsigned* qq = Bs2 + (kc + cl) * 36 + cb2 + q;
            unsigned bf2[2] = { qq[0], qq[4 * 36] };
            mma8t(acc2, af, bf2);
        }
    }

    {
        int row = b0e + rb2 + q;
        int c0  = n0e + cb2 + (cl << 1);
        out[(size_t)row * H_ + c0]           = tanhf(acc2[0] + ob[c0]);
        out[(size_t)row * H_ + c0 + 1]       = tanhf(acc2[1] + ob[c0 + 1]);
        out[(size_t)(row + 8) * H_ + c0]     = tanhf(acc2[2] + ob[c0]);
        out[(size_t)(row + 8) * H_ + c0 + 1] = tanhf(acc2[3] + ob[c0 + 1]);
    }
}

extern "C" void kernel_launch(void* const* d_in, const int* in_sizes, int n_in,
                              void* d_out, int out_size) {
    (void)in_sizes; (void)n_in; (void)out_size;
    const float* s_x = (const float*)d_in[0];
    const float* l_x = (const float*)d_in[1];
    // d_in[2]=dow, d_in[3]=hour : unused by the reference
    const float* s_W = (const float*)d_in[4];
    const float* s_b = (const float*)d_in[5];
    const float* l_W = (const float*)d_in[6];
    const float* l_b = (const float*)d_in[7];
    const float* oW  = (const float*)d_in[8];
    const float* ob  = (const float*)d_in[9];
    float* out = (float*)d_out;

    prep_x_kernel<<<(2 * B_ * T_ * I_ / 4 + 511) / 512, 512>>>(s_x, l_x);
    prep_w_kernel<<<(2 * G4_ * (K_ / 8) + 511) / 512, 512>>>(s_W, l_W);

    cudaFuncSetAttribute(dual_lstm_kernel,
                         cudaFuncAttributeMaxDynamicSharedMemorySize, SMEM_BYTES);
    dual_lstm_kernel<<<NBLK, NTHREADS, SMEM_BYTES>>>(s_b, l_b, oW, ob, out);
}

// round 15
// speedup vs baseline: 2.2898x; 1.0277x over previous
#include <cuda_runtime.h>
#include <cuda_fp16.h>
#include <cstdint>
#include <cstring>

// Dual LSTM B=512 T=128 I=128 H=512 — persistent kernel, 128 CTAs x 512 thr,
// fp16 mma m16n8k16 + ldmatrix, gate-interleaved W (register gate math),
// tanh.approx gates, 16-CTA scoped step barriers with acq_rel atomics.

#define B_   512
#define T_   128
#define I_   128
#define H_   512
#define K_   640
#define G4_  2048

#define NBLK     128
#define NTHREADS 512

#define A_STRIDE 20
#define B_STRIDE 20
#define A_WORDS  (128 * A_STRIDE)
#define B_WORDS  (128 * B_STRIDE)
#define STAGE_WORDS (A_WORDS + B_WORDS)
#define STAGE_BYTES (STAGE_WORDS * 4)
#define SMEM_BYTES  (2 * STAGE_BYTES)      // 40960

__device__ __half   g_x16[2][(size_t)B_ * T_ * I_];
__device__ __half   g_Wn[2][(size_t)G4_ * K_];   // [pcol][k], gate-interleaved pcol
__device__ __half   g_h16[2][2][(size_t)B_ * H_];
__device__ unsigned g_arrive[9];
__device__ unsigned g_release[9];

__device__ __forceinline__ unsigned f2tf32(float x) {
    unsigned u; asm("cvt.rna.tf32.f32 %0, %1;" : "=r"(u) : "f"(x)); return u;
}
__device__ __forceinline__ float tanh_a(float x) {
    float r; asm("tanh.approx.f32 %0, %1;" : "=f"(r) : "f"(x)); return r;
}
__device__ __forceinline__ float sigm_a(float x) {
    return fmaf(tanh_a(0.5f * x), 0.5f, 0.5f);
}

__device__ __forceinline__ void ldsm4(unsigned* r, uint32_t a) {
    asm volatile("ldmatrix.sync.aligned.m8n8.x4.shared.b16 {%0,%1,%2,%3}, [%4];"
                 : "=r"(r[0]), "=r"(r[1]), "=r"(r[2]), "=r"(r[3]) : "r"(a));
}
__device__ __forceinline__ uint32_t smem_u32(const void* p) {
    uint32_t a;
    asm("{ .reg .u64 t; cvta.to.shared.u64 t, %1; cvt.u32.u64 %0, t; }" : "=r"(a) : "l"(p));
    return a;
}

__device__ __forceinline__ void mma16(float* d, const unsigned* a, const unsigned* b) {
    asm volatile(
        "mma.sync.aligned.m16n8k16.row.col.f32.f16.f16.f32 "
        "{%0,%1,%2,%3}, {%4,%5,%6,%7}, {%8,%9}, {%0,%1,%2,%3};\n"
        : "+f"(d[0]), "+f"(d[1]), "+f"(d[2]), "+f"(d[3])
        : "r"(a[0]), "r"(a[1]), "r"(a[2]), "r"(a[3]), "r"(b[0]), "r"(b[1]));
}
__device__ __forceinline__ void mma8t(float* d, const unsigned* a, const unsigned* b) {
    asm volatile(
        "mma.sync.aligned.m16n8k8.row.col.f32.tf32.tf32.f32 "
        "{%0,%1,%2,%3}, {%4,%5,%6,%7}, {%8,%9}, {%0,%1,%2,%3};\n"
        : "+f"(d[0]), "+f"(d[1]), "+f"(d[2]), "+f"(d[3])
        : "r"(a[0]), "r"(a[1]), "r"(a[2]), "r"(a[3]), "r"(b[0]), "r"(b[1]));
}

// scoped grid barrier: release own stores via acq_rel arrive, acquire on poll
__device__ __forceinline__ void gsync(int idx, unsigned n) {
    __syncthreads();
    if (threadIdx.x == 0) {
        unsigned t;
        asm volatile("atom.add.acq_rel.gpu.global.u32 %0, [%1], 1;"
                     : "=r"(t) : "l"(&g_arrive[idx]) : "memory");
        t += 1u;
        unsigned gen = (t + n - 1u) / n;
        if (t == gen * n) {
            unsigned d;
            asm volatile("atom.add.release.gpu.global.u32 %0, [%1], 1;"
                         : "=r"(d) : "l"(&g_release[idx]) : "memory");
        }
        unsigned r;
        for (;;) {
            asm volatile("ld.acquire.gpu.u32 %0, [%1];" : "=r"(r) : "l"(&g_release[idx]) : "memory");
            if (r >= gen) break;
        }
    }
    __syncthreads();
}

__device__ __forceinline__ void st_h2(__half* p, float v0, float v1) {
    __half2 h = __floats2half2_rn(v0, v1);
    unsigned u; memcpy(&u, &h, 4);
    asm volatile("st.global.cg.u32 [%0], %1;" :: "l"(p), "r"(u) : "memory");
}

// pcol -> (gate, global hidden col) mapping (must match main kernel fragments)
__device__ __forceinline__ void pcol_map(int pcol, int& gate, int& n) {
    int slice = pcol >> 7;
    int lp    = pcol & 127;
    int wn    = lp >> 5;
    int r     = lp & 31;
    int nf    = r >> 3;
    int p     = r & 7;
    gate = (nf & 1) * 2 + (p & 1);
    n    = slice * 32 + wn * 8 + (nf >> 1) + (p >> 1) * 2;
}

// ---------------- prepass kernels ----------------
extern "C" __global__ void prep_x_kernel(const float* __restrict__ sx,
                                         const float* __restrict__ lx) {
    const int PER = B_ * T_ * I_ / 4;
    int i = blockIdx.x * blockDim.x + threadIdx.x;
    if (i >= 2 * PER) return;
    int cell = (i >= PER);
    int j = i - cell * PER;
    const float* src = cell ? lx : sx;
    float4 v = __ldg((const float4*)src + j);
    __half2* dst = (__half2*)(g_x16[cell]) + j * 2;
    dst[0] = __floats2half2_rn(v.x, v.y);
    dst[1] = __floats2half2_rn(v.z, v.w);
}

extern "C" __global__ void prep_w_kernel(const float* __restrict__ sW,
                                         const float* __restrict__ lW) {
    const int PER = G4_ * (K_ / 8);
    int i = blockIdx.x * blockDim.x + threadIdx.x;
    if (i >= 2 * PER) return;
    int cell = (i >= PER);
    int r = i - cell * PER;
    int pcol = r / (K_ / 8);
    int kg   = r % (K_ / 8);
    int gate, n;
    pcol_map(pcol, gate, n);
    const float* W = cell ? lW : sW;
    int wc = gate * H_ + n;
    __half tmp[8];
    #pragma unroll
    for (int k = 0; k < 8; ++k)
        tmp[k] = __float2half_rn(__ldg(W + (size_t)(kg * 8 + k) * G4_ + wc));
    uint4 o; memcpy(&o, tmp, 16);
    *(uint4*)(&g_Wn[cell][(size_t)pcol * K_ + kg * 8]) = o;
}

// ---------------- main persistent kernel ----------------
extern "C" __global__ void __launch_bounds__(NTHREADS, 1)
dual_lstm_kernel(const float* __restrict__ s_b, const float* __restrict__ l_b,
                 const float* __restrict__ oW,  const float* __restrict__ ob,
                 float* __restrict__ out)
{
    extern __shared__ unsigned char smem_raw[];
    unsigned* St = (unsigned*)smem_raw;
    const uint32_t smem_b32 = smem_u32(smem_raw);

    const int tid  = threadIdx.x;
    const int bid  = blockIdx.x;
    const int cell = bid >> 6;
    const int rr   = bid & 63;
    const int b0   = (rr >> 4) * 128;            // batch block
    const int n0   = (rr & 15) * 32;             // hidden block
    const int pbase = (rr & 15) * 128;           // pcol block in g_Wn
    const int grp  = (cell << 2) | (rr >> 4);    // 16-CTA sync group

    const __half* x16 = g_x16[cell];
    const __half* Wn  = g_Wn[cell];
    const float*  bb  = cell ? l_b : s_b;

    const int warp = tid >> 5, lane = tid & 31;
    const int wm = warp >> 2, wn = warp & 3;
    const int q  = lane >> 2, cl = lane & 3;

    // thread's owned hidden cols (adjacent pair) and bias
    const int ncol0 = n0 + wn * 8 + 2 * cl;
    float bias_g[2][4];                          // [j][gate]
    #pragma unroll
    for (int j = 0; j < 2; ++j)
        #pragma unroll
        for (int g = 0; g < 4; ++g)
            bias_g[j][g] = bb[g * H_ + ncol0 + j];

    // ---- zero initial h (parity 0) for this thread's owned cells ----
    #pragma unroll
    for (int mf = 0; mf < 2; ++mf)
        #pragma unroll
        for (int r = 0; r < 2; ++r) {
            int row = b0 + wm * 32 + mf * 16 + q + r * 8;
            st_h2(&g_h16[cell][0][(size_t)row * H_ + ncol0], 0.0f, 0.0f);
        }

    float c_st[8];
    #pragma unroll
    for (int i = 0; i < 8; ++i) c_st[i] = 0.0f;

    gsync(grp, 16);   // h zeros visible within sync group

    // fill index precompute
    const int fa_row = tid >> 2;
    const int fa_k8  = (tid & 3) << 3;
    const int fa_w   = fa_row * A_STRIDE + ((tid & 3) << 2);
    const int fb_lp  = tid >> 2;
    const int fb_kg  = (tid & 3) << 3;
    const int fb_w   = A_WORDS + fb_lp * B_STRIDE + ((tid & 3) << 2);
    const __half* WnC = Wn + (size_t)(pbase + fb_lp) * K_;

    const uint32_t a_frag_off = (uint32_t)((lane & 15) * (A_STRIDE * 4) + (lane >> 4) * 16);
    const uint32_t b_pcol     = (uint32_t)((lane >> 4) * 8 + (lane & 7));
    const uint32_t b_frag_off = (uint32_t)(A_WORDS * 4 + (wn * 32 + b_pcol) * (B_STRIDE * 4) +
                                           ((lane >> 3) & 1) * 16);
    const uint32_t sbase[2] = { smem_b32, smem_b32 + STAGE_BYTES };

    // ================== time loop ==================
    for (int t = 0; t < T_; ++t) {
        const __half* hread  = g_h16[cell][t & 1];
        __half*       hwrite = g_h16[cell][(t + 1) & 1];

        // init acc with bias (acc[mf][nb][2r+p] = bias_g[nb>>1][(nb&1)*2+p])
        float acc[2][4][4];
        #pragma unroll
        for (int a = 0; a < 2; ++a)
            #pragma unroll
            for (int nb = 0; nb < 4; ++nb)
                #pragma unroll
                for (int r = 0; r < 2; ++r) {
                    acc[a][nb][2 * r]     = bias_g[nb >> 1][(nb & 1) * 2];
                    acc[a][nb][2 * r + 1] = bias_g[nb >> 1][(nb & 1) * 2 + 1];
                }

        uint4 va, vb;
        va = __ldg((const uint4*)(x16 + ((size_t)(b0 + fa_row) * T_ + t) * I_ + fa_k8));
        vb = __ldg((const uint4*)(WnC + fb_kg));
        *(uint4*)(St + fa_w) = va;
        *(uint4*)(St + fb_w) = vb;
        __syncthreads();

        for (int kt = 0; kt < 20; ++kt) {
            const int s = kt & 1;
            if (kt < 19) {
                const int k0n = (kt + 1) * 32;
                if (k0n < I_)
                    va = __ldg((const uint4*)(x16 + ((size_t)(b0 + fa_row) * T_ + t) * I_ +
                                              k0n + fa_k8));
                else
                    va = __ldcg((const uint4*)(hread + (size_t)(b0 + fa_row) * H_ +
                                               (k0n - I_) + fa_k8));
                vb = __ldg((const uint4*)(WnC + k0n + fb_kg));
            }
            {
                const uint32_t sA = sbase[s];
                #pragma unroll
                for (int kc = 0; kc < 2; ++kc) {
                    unsigned af[2][4], bf[4][4];
                    #pragma unroll
                    for (int mf = 0; mf < 2; ++mf)
                        ldsm4(af[mf], sA + (wm * 32 + mf * 16) * (A_STRIDE * 4) +
                                       a_frag_off + kc * 32);
                    #pragma unroll
                    for (int nfp = 0; nfp < 2; ++nfp)
                        ldsm4(bf[nfp * 2], sA + b_frag_off + nfp * (16 * B_STRIDE * 4) +
                                            kc * 32);
                    #pragma unroll
                    for (int mf = 0; mf < 2; ++mf) {
                        #pragma unroll
                        for (int nfp = 0; nfp < 2; ++nfp) {
                            mma16(acc[mf][nfp * 2],     af[mf], &bf[nfp * 2][0]);
                            mma16(acc[mf][nfp * 2 + 1], af[mf], &bf[nfp * 2][2]);
                        }
                    }
                }
            }
            if (kt < 19) {
                unsigned* Ds = St + (s ^ 1) * STAGE_WORDS;
                *(uint4*)(Ds + fa_w) = va;
                *(uint4*)(Ds + fb_w) = vb;
            }
            __syncthreads();
        }

        // ---- gate math fully in registers (tanh.approx) ----
        #pragma unroll
        for (int mf = 0; mf < 2; ++mf) {
            #pragma unroll
            for (int r = 0; r < 2; ++r) {
                float h01[2];
                #pragma unroll
                for (int j = 0; j < 2; ++j) {
                    float f  = acc[mf][j * 2][2 * r];
                    float ii = acc[mf][j * 2][2 * r + 1];
                    float o  = acc[mf][j * 2 + 1][2 * r];
                    float cd = acc[mf][j * 2 + 1][2 * r + 1];
                    int ci = mf * 4 + r * 2 + j;
                    float c = sigm_a(f) * c_st[ci] + sigm_a(ii) * tanh_a(cd);
                    c_st[ci] = c;
                    h01[j] = sigm_a(o) * tanh_a(c);
                }
                int row = b0 + wm * 32 + mf * 16 + q + r * 8;
                st_h2(&hwrite[(size_t)row * H_ + ncol0], h01[0], h01[1]);
            }
        }
        gsync(grp, 16);
    }

    gsync(8, 128);   // both cells' final h visible everywhere

    // ================== epilogue: out = tanh([sh,lh] @ oW + ob) ==================
    const __half* hs = g_h16[0][0];
    const __half* hl = g_h16[1][0];
    const int b0e = (bid >> 4) * 64;
    const int n0e = (bid & 15) * 32;
    unsigned* As2 = (unsigned*)smem_raw;    // [64][36] tf32
    unsigned* Bs2 = As2 + 64 * 36;          // [32][36] tf32

    const int wm2 = warp & 3;
    const int wn2 = warp >> 2;
    const int rb2 = wm2 * 16;
    const int cb2 = wn2 * 8;
    float acc2[4];
    #pragma unroll
    for (int r = 0; r < 4; ++r) acc2[r] = 0.0f;

    for (int kt = 0; kt < 32; ++kt) {
        const int k0 = kt * 32;
        __syncthreads();
        {
            int m  = tid >> 3;
            int kk = (tid & 7) << 2;
            int k  = k0 + kk;
            const __half* hp = (k < H_) ? (hs + (size_t)(b0e + m) * H_ + k)
                                        : (hl + (size_t)(b0e + m) * H_ + (k - H_));
            uint2 u = __ldcg((const uint2*)hp);
            __half2 p0, p1;
            memcpy(&p0, &u.x, 4);
            memcpy(&p1, &u.y, 4);
            unsigned* d = As2 + m * 36 + kk;
            d[0] = __float_as_uint(__low2float(p0));
            d[1] = __float_as_uint(__high2float(p0));
            d[2] = __float_as_uint(__low2float(p1));
            d[3] = __float_as_uint(__high2float(p1));
        }
        if (tid < 256) {
            int kk = tid >> 3;
            int c  = (tid & 7) << 2;
            float4 v = __ldg((const float4*)(oW + (size_t)(k0 + kk) * H_ + n0e + c));
            unsigned* d = Bs2 + kk * 36 + c;
            d[0] = f2tf32(v.x); d[1] = f2tf32(v.y);
            d[2] = f2tf32(v.z); d[3] = f2tf32(v.w);
        }
        __syncthreads();
        #pragma unroll
        for (int kc = 0; kc < 32; kc += 8) {
            unsigned af[4];
            const unsigned* p = As2 + (rb2 + q) * 36 + kc + cl;
            af[0] = p[0]; af[1] = p[8 * 36]; af[2] = p[4]; af[3] = p[8 * 36 + 4];
            const unsigned* qq = Bs2 + (kc + cl) * 36 + cb2 + q;
            unsigned bf2[2] = { qq[0], qq[4 * 36] };
            mma8t(acc2, af, bf2);
        }
    }

    {
        int row = b0e + rb2 + q;
        int c0  = n0e + cb2 + (cl << 1);
        out[(size_t)row * H_ + c0]           = tanhf(acc2[0] + ob[c0]);
        out[(size_t)row * H_ + c0 + 1]       = tanhf(acc2[1] + ob[c0 + 1]);
        out[(size_t)(row + 8) * H_ + c0]     = tanhf(acc2[2] + ob[c0]);
        out[(size_t)(row + 8) * H_ + c0 + 1] = tanhf(acc2[3] + ob[c0 + 1]);
    }
}

extern "C" void kernel_launch(void* const* d_in, const int* in_sizes, int n_in,
                              void* d_out, int out_size) {
    (void)in_sizes; (void)n_in; (void)out_size;
    const float* s_x = (const float*)d_in[0];
    const float* l_x = (const float*)d_in[1];
    // d_in[2]=dow, d_in[3]=hour : unused by the reference
    const float* s_W = (const float*)d_in[4];
    const float* s_b = (const float*)d_in[5];
    const float* l_W = (const float*)d_in[6];
    const float* l_b = (const float*)d_in[7];
    const float* oW  = (const float*)d_in[8];
    const float* ob  = (const float*)d_in[9];
    float* out = (float*)d_out;

    prep_x_kernel<<<(2 * B_ * T_ * I_ / 4 + 511) / 512, 512>>>(s_x, l_x);
    prep_w_kernel<<<(2 * G4_ * (K_ / 8) + 511) / 512, 512>>>(s_W, l_W);

    cudaFuncSetAttribute(dual_lstm_kernel,
                         cudaFuncAttributeMaxDynamicSharedMemorySize, SMEM_BYTES);
    dual_lstm_kernel<<<NBLK, NTHREADS, SMEM_BYTES>>>(s_b, l_b, oW, ob, out);
}

// round 16
// speedup vs baseline: 3.1180x; 1.3617x over previous
#include <cuda_runtime.h>
#include <cuda_fp16.h>
#include <cstdint>
#include <cstring>

// Dual LSTM B=512 T=128 I=128 H=512 — persistent kernel, 128 CTAs x 512 thr.
// W resident in smem for the whole time loop (162 KB, padded stride);
// A via 4-stage cp.async ring; fp16 mma m16n8k16 + ldmatrix; register gate math.

#define B_   512
#define T_   128
#define I_   128
#define H_   512
#define K_   640
#define G4_  2048

#define NBLK     128
#define NTHREADS 512

#define W_STRIDE 324                        // words per pcol row (4-word bank step)
#define W_BYTES  (128 * W_STRIDE * 4)       // 165888
#define A_STRIDE 20
#define A_STAGE_BYTES (128 * A_STRIDE * 4)  // 10240
#define A_OFF    W_BYTES
#define SMEM_BYTES (W_BYTES + 4 * A_STAGE_BYTES)   // 206848

__device__ __half   g_x16[2][(size_t)B_ * T_ * I_];
__device__ __half   g_Wn[2][(size_t)G4_ * K_];   // [pcol][k], gate-interleaved pcol
__device__ __half   g_h16[2][2][(size_t)B_ * H_];
__device__ unsigned g_arrive[9];
__device__ unsigned g_release[9];

__device__ __forceinline__ unsigned f2tf32(float x) {
    unsigned u; asm("cvt.rna.tf32.f32 %0, %1;" : "=r"(u) : "f"(x)); return u;
}
__device__ __forceinline__ float tanh_a(float x) {
    float r; asm("tanh.approx.f32 %0, %1;" : "=f"(r) : "f"(x)); return r;
}
__device__ __forceinline__ float sigm_a(float x) {
    return fmaf(tanh_a(0.5f * x), 0.5f, 0.5f);
}

__device__ __forceinline__ void ldsm4(unsigned* r, uint32_t a) {
    asm volatile("ldmatrix.sync.aligned.m8n8.x4.shared.b16 {%0,%1,%2,%3}, [%4];"
                 : "=r"(r[0]), "=r"(r[1]), "=r"(r[2]), "=r"(r[3]) : "r"(a));
}
__device__ __forceinline__ uint32_t smem_u32(const void* p) {
    uint32_t a;
    asm("{ .reg .u64 t; cvta.to.shared.u64 t, %1; cvt.u32.u64 %0, t; }" : "=r"(a) : "l"(p));
    return a;
}
__device__ __forceinline__ void cpa16(uint32_t saddr, const void* g) {
    asm volatile("cp.async.cg.shared.global [%0], [%1], 16;"
                 :: "r"(saddr), "l"(g) : "memory");
}
#define CP_COMMIT() asm volatile("cp.async.commit_group;" ::: "memory")
#define CP_WAIT2()  asm volatile("cp.async.wait_group 2;" ::: "memory")

__device__ __forceinline__ void mma16(float* d, const unsigned* a, const unsigned* b) {
    asm volatile(
        "mma.sync.aligned.m16n8k16.row.col.f32.f16.f16.f32 "
        "{%0,%1,%2,%3}, {%4,%5,%6,%7}, {%8,%9}, {%0,%1,%2,%3};\n"
        : "+f"(d[0]), "+f"(d[1]), "+f"(d[2]), "+f"(d[3])
        : "r"(a[0]), "r"(a[1]), "r"(a[2]), "r"(a[3]), "r"(b[0]), "r"(b[1]));
}
__device__ __forceinline__ void mma8t(float* d, const unsigned* a, const unsigned* b) {
    asm volatile(
        "mma.sync.aligned.m16n8k8.row.col.f32.tf32.tf32.f32 "
        "{%0,%1,%2,%3}, {%4,%5,%6,%7}, {%8,%9}, {%0,%1,%2,%3};\n"
        : "+f"(d[0]), "+f"(d[1]), "+f"(d[2]), "+f"(d[3])
        : "r"(a[0]), "r"(a[1]), "r"(a[2]), "r"(a[3]), "r"(b[0]), "r"(b[1]));
}

__device__ __forceinline__ void gsync(int idx, unsigned n) {
    __syncthreads();
    if (threadIdx.x == 0) {
        unsigned t;
        asm volatile("atom.add.acq_rel.gpu.global.u32 %0, [%1], 1;"
                     : "=r"(t) : "l"(&g_arrive[idx]) : "memory");
        t += 1u;
        unsigned gen = (t + n - 1u) / n;
        if (t == gen * n) {
            unsigned d;
            asm volatile("atom.add.release.gpu.global.u32 %0, [%1], 1;"
                         : "=r"(d) : "l"(&g_release[idx]) : "memory");
        }
        unsigned r;
        for (;;) {
            asm volatile("ld.acquire.gpu.u32 %0, [%1];" : "=r"(r) : "l"(&g_release[idx]) : "memory");
            if (r >= gen) break;
        }
    }
    __syncthreads();
}

__device__ __forceinline__ void st_h2(__half* p, float v0, float v1) {
    __half2 h = __floats2half2_rn(v0, v1);
    unsigned u; memcpy(&u, &h, 4);
    asm volatile("st.global.cg.u32 [%0], %1;" :: "l"(p), "r"(u) : "memory");
}

// pcol -> (gate, global hidden col) mapping (must match main kernel fragments)
__device__ __forceinline__ void pcol_map(int pcol, int& gate, int& n) {
    int slice = pcol >> 7;
    int lp    = pcol & 127;
    int wn    = lp >> 5;
    int r     = lp & 31;
    int nf    = r >> 3;
    int p     = r & 7;
    gate = (nf & 1) * 2 + (p & 1);
    n    = slice * 32 + wn * 8 + (nf >> 1) + (p >> 1) * 2;
}

// ---------------- prepass kernels ----------------
extern "C" __global__ void prep_x_kernel(const float* __restrict__ sx,
                                         const float* __restrict__ lx) {
    const int PER = B_ * T_ * I_ / 4;
    int i = blockIdx.x * blockDim.x + threadIdx.x;
    if (i >= 2 * PER) return;
    int cell = (i >= PER);
    int j = i - cell * PER;
    const float* src = cell ? lx : sx;
    float4 v = __ldg((const float4*)src + j);
    __half2* dst = (__half2*)(g_x16[cell]) + j * 2;
    dst[0] = __floats2half2_rn(v.x, v.y);
    dst[1] = __floats2half2_rn(v.z, v.w);
}

extern "C" __global__ void prep_w_kernel(const float* __restrict__ sW,
                                         const float* __restrict__ lW) {
    const int PER = G4_ * (K_ / 8);
    int i = blockIdx.x * blockDim.x + threadIdx.x;
    if (i >= 2 * PER) return;
    int cell = (i >= PER);
    int r = i - cell * PER;
    int pcol = r / (K_ / 8);
    int kg   = r % (K_ / 8);
    int gate, n;
    pcol_map(pcol, gate, n);
    const float* W = cell ? lW : sW;
    int wc = gate * H_ + n;
    __half tmp[8];
    #pragma unroll
    for (int k = 0; k < 8; ++k)
        tmp[k] = __float2half_rn(__ldg(W + (size_t)(kg * 8 + k) * G4_ + wc));
    uint4 o; memcpy(&o, tmp, 16);
    *(uint4*)(&g_Wn[cell][(size_t)pcol * K_ + kg * 8]) = o;
}

// ---------------- main persistent kernel ----------------
extern "C" __global__ void __launch_bounds__(NTHREADS, 1)
dual_lstm_kernel(const float* __restrict__ s_b, const float* __restrict__ l_b,
                 const float* __restrict__ oW,  const float* __restrict__ ob,
                 float* __restrict__ out)
{
    extern __shared__ unsigned char smem_raw[];
    unsigned* Wsm = (unsigned*)smem_raw;
    const uint32_t smem_b32 = smem_u32(smem_raw);

    const int tid  = threadIdx.x;
    const int bid  = blockIdx.x;
    const int cell = bid >> 6;
    const int rr   = bid & 63;
    const int b0   = (rr >> 4) * 128;
    const int n0   = (rr & 15) * 32;
    const int pbase = (rr & 15) * 128;
    const int grp  = (cell << 2) | (rr >> 4);

    const __half* x16 = g_x16[cell];
    const __half* Wn  = g_Wn[cell];
    const float*  bb  = cell ? l_b : s_b;

    const int warp = tid >> 5, lane = tid & 31;
    const int wm = warp >> 2, wn = warp & 3;
    const int q  = lane >> 2, cl = lane & 3;

    // ---- load W slice into smem once (gate-interleaved [pcol][k], stride 324) ----
    for (int i = tid; i < 128 * 80; i += NTHREADS) {
        int pcol = i / 80, kg = i % 80;        // kg = 16B group (8 halves)
        uint4 v = __ldg((const uint4*)(Wn + (size_t)(pbase + pcol) * K_ + kg * 8));
        *(uint4*)(Wsm + pcol * W_STRIDE + kg * 4) = v;
    }

    // thread's owned hidden cols + bias
    const int ncol0 = n0 + wn * 8 + 2 * cl;
    float bias_g[2][4];
    #pragma unroll
    for (int j = 0; j < 2; ++j)
        #pragma unroll
        for (int g = 0; g < 4; ++g)
            bias_g[j][g] = bb[g * H_ + ncol0 + j];

    // zero initial h (parity 0)
    #pragma unroll
    for (int mf = 0; mf < 2; ++mf)
        #pragma unroll
        for (int r = 0; r < 2; ++r) {
            int row = b0 + wm * 32 + mf * 16 + q + r * 8;
            st_h2(&g_h16[cell][0][(size_t)row * H_ + ncol0], 0.0f, 0.0f);
        }

    float c_st[8];
    #pragma unroll
    for (int i = 0; i < 8; ++i) c_st[i] = 0.0f;

    gsync(grp, 16);   // W smem + h zeros done; h visible within sync group

    // A fill / fragment constants
    const int fa_row = tid >> 2;
    const int fa_k8  = (tid & 3) << 3;
    const uint32_t fa_woff = (uint32_t)(fa_row * 80 + (tid & 3) * 16);   // bytes in stage
    const uint32_t a_frag_off = (uint32_t)((lane & 15) * 80 + (lane >> 4) * 16);
    const uint32_t b_pcol = (uint32_t)((lane >> 4) * 8 + (lane & 7));
    const uint32_t b_base = smem_b32 + (wn * 32 + b_pcol) * (W_STRIDE * 4) +
                            ((lane >> 3) & 1) * 16;
    const uint32_t a_stage_base = smem_b32 + A_OFF;

    // ================== time loop ==================
    for (int t = 0; t < T_; ++t) {
        const __half* hread  = g_h16[cell][t & 1];
        __half*       hwrite = g_h16[cell][(t + 1) & 1];
        const __half* x_t    = x16 + ((size_t)(b0 + fa_row) * T_ + t) * I_;

        float acc[2][4][4];
        #pragma unroll
        for (int a = 0; a < 2; ++a)
            #pragma unroll
            for (int nb = 0; nb < 4; ++nb)
                #pragma unroll
                for (int r = 0; r < 2; ++r) {
                    acc[a][nb][2 * r]     = bias_g[nb >> 1][(nb & 1) * 2];
                    acc[a][nb][2 * r + 1] = bias_g[nb >> 1][(nb & 1) * 2 + 1];
                }

        // prologue: issue x tiles 0..2 into stages 0..2
        #pragma unroll
        for (int p = 0; p < 3; ++p) {
            cpa16(a_stage_base + p * A_STAGE_BYTES + fa_woff, x_t + p * 32 + fa_k8);
            CP_COMMIT();
        }

        for (int kt = 0; kt < 20; ++kt) {
            CP_WAIT2();
            __syncthreads();
            // issue tile kt+3 into stage (kt+3)&3 (freed by tile kt-1)
            if (kt < 17) {
                const int k0n = (kt + 3) * 32;
                const __half* src = (k0n < I_)
                    ? (x_t + k0n + fa_k8)
                    : (hread + (size_t)(b0 + fa_row) * H_ + (k0n - I_) + fa_k8);
                cpa16(a_stage_base + ((kt + 3) & 3) * A_STAGE_BYTES + fa_woff, src);
            }
            CP_COMMIT();
            // compute tile kt: A from stage kt&3, B from resident W smem
            {
                const uint32_t sA = a_stage_base + (kt & 3) * A_STAGE_BYTES;
                const uint32_t bk = b_base + kt * 64;
                #pragma unroll
                for (int kc = 0; kc < 2; ++kc) {
                    unsigned af[2][4], bf[4][4];
                    #pragma unroll
                    for (int mf = 0; mf < 2; ++mf)
                        ldsm4(af[mf], sA + (wm * 32 + mf * 16) * 80 + a_frag_off + kc * 32);
                    #pragma unroll
                    for (int nfp = 0; nfp < 2; ++nfp)
                        ldsm4(bf[nfp * 2], bk + nfp * (16 * W_STRIDE * 4) + kc * 32);
                    #pragma unroll
                    for (int mf = 0; mf < 2; ++mf) {
                        #pragma unroll
                        for (int nfp = 0; nfp < 2; ++nfp) {
                            mma16(acc[mf][nfp * 2],     af[mf], &bf[nfp * 2][0]);
                            mma16(acc[mf][nfp * 2 + 1], af[mf], &bf[nfp * 2][2]);
                        }
                    }
                }
            }
        }

        // ---- gate math fully in registers (tanh.approx) ----
        #pragma unroll
        for (int mf = 0; mf < 2; ++mf) {
            #pragma unroll
            for (int r = 0; r < 2; ++r) {
                float h01[2];
                #pragma unroll
                for (int j = 0; j < 2; ++j) {
                    float f  = acc[mf][j * 2][2 * r];
                    float ii = acc[mf][j * 2][2 * r + 1];
                    float o  = acc[mf][j * 2 + 1][2 * r];
                    float cd = acc[mf][j * 2 + 1][2 * r + 1];
                    int ci = mf * 4 + r * 2 + j;
                    float c = sigm_a(f) * c_st[ci] + sigm_a(ii) * tanh_a(cd);
                    c_st[ci] = c;
                    h01[j] = sigm_a(o) * tanh_a(c);
                }
                int row = b0 + wm * 32 + mf * 16 + q + r * 8;
                st_h2(&hwrite[(size_t)row * H_ + ncol0], h01[0], h01[1]);
            }
        }
        gsync(grp, 16);
    }

    gsync(8, 128);   // both cells' final h visible everywhere

    // ================== epilogue: out = tanh([sh,lh] @ oW + ob) ==================
    const __half* hs = g_h16[0][0];
    const __half* hl = g_h16[1][0];
    const int b0e = (bid >> 4) * 64;
    const int n0e = (bid & 15) * 32;
    unsigned* As2 = (unsigned*)smem_raw;    // [64][36] tf32
    unsigned* Bs2 = As2 + 64 * 36;          // [32][36] tf32

    const int wm2 = warp & 3;
    const int wn2 = warp >> 2;
    const int rb2 = wm2 * 16;
    const int cb2 = wn2 * 8;
    float acc2[4];
    #pragma unroll
    for (int r = 0; r < 4; ++r) acc2[r] = 0.0f;

    for (int kt = 0; kt < 32; ++kt) {
        const int k0 = kt * 32;
        __syncthreads();
        {
            int m  = tid >> 3;
            int kk = (tid & 7) << 2;
            int k  = k0 + kk;
            const __half* hp = (k < H_) ? (hs + (size_t)(b0e + m) * H_ + k)
                                        : (hl + (size_t)(b0e + m) * H_ + (k - H_));
            uint2 u = __ldcg((const uint2*)hp);
            __half2 p0, p1;
            memcpy(&p0, &u.x, 4);
            memcpy(&p1, &u.y, 4);
            unsigned* d = As2 + m * 36 + kk;
            d[0] = __float_as_uint(__low2float(p0));
            d[1] = __float_as_uint(__high2float(p0));
            d[2] = __float_as_uint(__low2float(p1));
            d[3] = __float_as_uint(__high2float(p1));
        }
        if (tid < 256) {
            int kk = tid >> 3;
            int c  = (tid & 7) << 2;
            float4 v = __ldg((const float4*)(oW + (size_t)(k0 + kk) * H_ + n0e + c));
            unsigned* d = Bs2 + kk * 36 + c;
            d[0] = f2tf32(v.x); d[1] = f2tf32(v.y);
            d[2] = f2tf32(v.z); d[3] = f2tf32(v.w);
        }
        __syncthreads();
        #pragma unroll
        for (int kc = 0; kc < 32; kc += 8) {
            unsigned af[4];
            const unsigned* p = As2 + (rb2 + q) * 36 + kc + cl;
            af[0] = p[0]; af[1] = p[8 * 36]; af[2] = p[4]; af[3] = p[8 * 36 + 4];
            const unsigned* qq = Bs2 + (kc + cl) * 36 + cb2 + q;
            unsigned bf2[2] = { qq[0], qq[4 * 36] };
            mma8t(acc2, af, bf2);
        }
    }

    {
        int row = b0e + rb2 + q;
        int c0  = n0e + cb2 + (cl << 1);
        out[(size_t)row * H_ + c0]           = tanhf(acc2[0] + ob[c0]);
        out[(size_t)row * H_ + c0 + 1]       = tanhf(acc2[1] + ob[c0 + 1]);
        out[(size_t)(row + 8) * H_ + c0]     = tanhf(acc2[2] + ob[c0]);
        out[(size_t)(row + 8) * H_ + c0 + 1] = tanhf(acc2[3] + ob[c0 + 1]);
    }
}

extern "C" void kernel_launch(void* const* d_in, const int* in_sizes, int n_in,
                              void* d_out, int out_size) {
    (void)in_sizes; (void)n_in; (void)out_size;
    const float* s_x = (const float*)d_in[0];
    const float* l_x = (const float*)d_in[1];
    // d_in[2]=dow, d_in[3]=hour : unused by the reference
    const float* s_W = (const float*)d_in[4];
    const float* s_b = (const float*)d_in[5];
    const float* l_W = (const float*)d_in[6];
    const float* l_b = (const float*)d_in[7];
    const float* oW  = (const float*)d_in[8];
    const float* ob  = (const float*)d_in[9];
    float* out = (float*)d_out;

    prep_x_kernel<<<(2 * B_ * T_ * I_ / 4 + 511) / 512, 512>>>(s_x, l_x);
    prep_w_kernel<<<(2 * G4_ * (K_ / 8) + 511) / 512, 512>>>(s_W, l_W);

    cudaFuncSetAttribute(dual_lstm_kernel,
                         cudaFuncAttributeMaxDynamicSharedMemorySize, SMEM_BYTES);
    dual_lstm_kernel<<<NBLK, NTHREADS, SMEM_BYTES>>>(s_b, l_b, oW, ob, out);
}